// round 2
// baseline (speedup 1.0000x reference)
#include <cuda_runtime.h>
#include <math.h>

#define H    16
#define HD   64
#define MEMS 32768
#define IPQ  8
#define BB   4
#define NN   512
#define DIN  1024
#define DOUT 1024
#define BNR  (BB*NN)        // 2048 rows total
#define MOLD (MEMS - BNR)   // 30720
#define SCALE 0.125f

// ------------------------- scratch (device globals) -------------------------
__device__ float g_q  [BNR*DIN];
__device__ float g_k  [BNR*DIN];
__device__ float g_v  [BNR*DOUT];
__device__ float g_w  [BNR*DOUT];
__device__ float g_ao [BNR*DOUT];
__device__ float g_aom[BNR*DOUT];
__device__ float g_c1 [BNR*DOUT];
__device__ float g_c2 [BNR*DOUT];
__device__ float g_km [(size_t)BB*(NN*IPQ)*DIN];
__device__ float g_vm [(size_t)BB*(NN*IPQ)*DOUT];
__device__ int   g_idx[H*BNR*IPQ];

// ------------------------- generic SGEMM: C = A * B^T ------------------------
// A [M,K] row-major, B [N,K] row-major, C [M,N]. 64x64x16 tiles, 256 thr, 4x4.
__global__ void sgemm_abt(const float* __restrict__ A, const float* __restrict__ B,
                          float* __restrict__ C, int M, int N, int K,
                          const float* __restrict__ bias, int do_sigmoid)
{
    __shared__ float As[16][68];
    __shared__ float Bs[16][68];
    int t  = threadIdx.x;
    int tx = t & 15, ty = t >> 4;
    int row0 = blockIdx.y * 64, col0 = blockIdx.x * 64;
    float acc[4][4] = {};
    for (int k0 = 0; k0 < K; k0 += 16) {
        for (int i = t; i < 64*16; i += 256) {
            int r = i >> 4, c = i & 15;
            As[c][r] = A[(size_t)(row0 + r) * K + k0 + c];
        }
        for (int i = t; i < 64*16; i += 256) {
            int r = i >> 4, c = i & 15;
            Bs[c][r] = B[(size_t)(col0 + r) * K + k0 + c];
        }
        __syncthreads();
        #pragma unroll
        for (int kk = 0; kk < 16; kk++) {
            float a[4], b[4];
            #pragma unroll
            for (int u = 0; u < 4; u++) a[u] = As[kk][ty*4 + u];
            #pragma unroll
            for (int u = 0; u < 4; u++) b[u] = Bs[kk][tx*4 + u];
            #pragma unroll
            for (int i = 0; i < 4; i++)
                #pragma unroll
                for (int j = 0; j < 4; j++)
                    acc[i][j] += a[i] * b[j];
        }
        __syncthreads();
    }
    #pragma unroll
    for (int i = 0; i < 4; i++) {
        int r = row0 + ty*4 + i;
        #pragma unroll
        for (int j = 0; j < 4; j++) {
            int c = col0 + tx*4 + j;
            float v = acc[i][j];
            if (bias) v += bias[c];
            if (do_sigmoid) v = 1.0f / (1.0f + __expf(-v));
            C[(size_t)r * N + c] = v;
        }
    }
}

// --------------- sims + top-8: per head, q[2048,64] x mem[32768,64] ----------
// grid (32, 16): blockIdx.x = 64-query tile, blockIdx.y = head. 256 threads.
// smem: Qs[64][68] q-major, Ks[64][65] d-major, Ss[64][65].
__global__ void sims_topk(const float* __restrict__ Qbuf, const float* __restrict__ Kbuf,
                          const float* __restrict__ kmem0)
{
    extern __shared__ float sm[];
    float* Qs_ = sm;                  // 64*68
    float* Ks_ = Qs_ + 64*68;         // 64*65
    float* Ss_ = Ks_ + 64*65;         // 64*65
    #define QSI(r,c) Qs_[(r)*68 + (c)]
    #define KSI(d,j) Ks_[(d)*65 + (j)]
    #define SSI(q,j) Ss_[(q)*65 + (j)]

    int t  = threadIdx.x;
    int h  = blockIdx.y;
    int q0 = blockIdx.x * 64;

    for (int i = t; i < 64*64; i += 256) {
        int r = i >> 6, c = i & 63;
        QSI(r, c) = Qbuf[(size_t)(q0 + r) * DIN + h*HD + c];
    }

    float tv[8]; int ti[8];
    #pragma unroll
    for (int p = 0; p < 8; p++) { tv[p] = -INFINITY; ti[p] = 0; }
    float tmin = -INFINITY; int tpos = 0;

    int qg = t >> 4;          // 0..15 -> 4 query rows
    int jg = t & 15;          // 0..15 -> 4 key cols
    int qs_row = t & 63;      // scan row
    int cbase  = (t >> 6) * 16;

    for (int tile = 0; tile < MEMS/64; tile++) {
        int j0 = tile * 64;
        for (int i = t; i < 64*64; i += 256) {
            int r = i >> 6, c = i & 63;
            int gk = j0 + r;
            float val;
            if (gk < MOLD) val = kmem0[((size_t)h*MEMS + gk + BNR)*HD + c];
            else           val = Kbuf[(size_t)(gk - MOLD)*DIN + h*HD + c];
            KSI(c, r) = val;
        }
        __syncthreads();
        float acc[4][4] = {};
        #pragma unroll 16
        for (int d = 0; d < 64; d++) {
            float a0 = QSI(qg*4+0, d), a1 = QSI(qg*4+1, d);
            float a2 = QSI(qg*4+2, d), a3 = QSI(qg*4+3, d);
            float b0 = KSI(d, jg*4+0), b1 = KSI(d, jg*4+1);
            float b2 = KSI(d, jg*4+2), b3 = KSI(d, jg*4+3);
            acc[0][0] += a0*b0; acc[0][1] += a0*b1; acc[0][2] += a0*b2; acc[0][3] += a0*b3;
            acc[1][0] += a1*b0; acc[1][1] += a1*b1; acc[1][2] += a1*b2; acc[1][3] += a1*b3;
            acc[2][0] += a2*b0; acc[2][1] += a2*b1; acc[2][2] += a2*b2; acc[2][3] += a2*b3;
            acc[3][0] += a3*b0; acc[3][1] += a3*b1; acc[3][2] += a3*b2; acc[3][3] += a3*b3;
        }
        #pragma unroll
        for (int i = 0; i < 4; i++)
            #pragma unroll
            for (int j = 0; j < 4; j++)
                SSI(qg*4+i, jg*4+j) = acc[i][j];
        __syncthreads();
        #pragma unroll
        for (int jj = 0; jj < 16; jj++) {
            float s = SSI(qs_row, cbase + jj);
            if (s > tmin) {
                tv[tpos] = s; ti[tpos] = j0 + cbase + jj;
                tmin = tv[0]; tpos = 0;
                #pragma unroll
                for (int p = 1; p < 8; p++)
                    if (tv[p] < tmin) { tmin = tv[p]; tpos = p; }
            }
        }
        // no sync needed here: next load writes Ks only (not read by scan);
        // next compute (which writes Ss) is fenced by the post-load sync.
    }
    __syncthreads();
    // dump partial lists & merge 4 per row
    float* cval = Qs_;            // 2048 floats
    int*   cidx = (int*)Ks_;      // 2048 ints
    #pragma unroll
    for (int p = 0; p < 8; p++) { cval[t*8 + p] = tv[p]; cidx[t*8 + p] = ti[p]; }
    __syncthreads();
    if (t < 64) {
        float fv[8]; int fi[8]; float fmin = -INFINITY; int fpos = 0;
        #pragma unroll
        for (int p = 0; p < 8; p++) { fv[p] = -INFINITY; fi[p] = 0; }
        for (int g = 0; g < 4; g++) {
            int src = t + g*64;
            #pragma unroll
            for (int p = 0; p < 8; p++) {
                float s = cval[src*8 + p]; int id = cidx[src*8 + p];
                if (s > fmin) {
                    fv[fpos] = s; fi[fpos] = id;
                    fmin = fv[0]; fpos = 0;
                    #pragma unroll
                    for (int pp = 1; pp < 8; pp++)
                        if (fv[pp] < fmin) { fmin = fv[pp]; fpos = pp; }
                }
            }
        }
        #pragma unroll
        for (int p = 0; p < 8; p++)
            g_idx[((size_t)h*BNR + q0 + t)*IPQ + p] = fi[p];
    }
    #undef QSI
    #undef KSI
    #undef SSI
}

// --------------------- gather k_m / v_m from idx -----------------------------
__global__ void gather_kernel(const float* __restrict__ kmem0, const float* __restrict__ vmem0)
{
    int e = blockIdx.x * 256 + threadIdx.x;     // < 4*4096*1024 = 2^24
    int c  = e & 1023;
    int m2 = (e >> 10) & 4095;
    int b  = e >> 22;
    int h = c >> 6, d = c & 63;
    int nq = m2 >> 3, ip = m2 & 7;
    int f = b * NN + nq;
    int row = g_idx[((size_t)h*BNR + f)*IPQ + ip];
    float kv, vv;
    if (row < MOLD) {
        size_t base = ((size_t)h*MEMS + row + BNR)*HD + d;
        kv = kmem0[base]; vv = vmem0[base];
    } else {
        int fl = row - MOLD;
        size_t base = (size_t)fl*DIN + h*HD + d;
        kv = g_k[base]; vv = g_v[base];
    }
    g_km[e] = kv;
    g_vm[e] = vv;
}

// ------------------- flash attention (shared for a, a_m) ---------------------
// grid (NN/32, H, BB), 256 threads. K/V layout [b, m, H*HD].
__global__ void flash_attn(const float* __restrict__ Qbuf, const float* __restrict__ Ksrc,
                           const float* __restrict__ Vsrc, float* __restrict__ Obuf, int m)
{
    extern __shared__ float sm[];
    float* Qs_ = sm;                     // [32][68]
    float* Ks_ = Qs_ + 32*68;            // [64][65] d-major
    float* Vs_ = Ks_ + 64*65;            // [64][64] j-major
    float* Ss_ = Vs_ + 64*64;            // [32][65]
    float* mrow = Ss_ + 32*65;
    float* lrow = mrow + 32;
    float* fac  = lrow + 32;
    #define QSI(q,d) Qs_[(q)*68 + (d)]
    #define KSI(d,j) Ks_[(d)*65 + (j)]
    #define VSI(j,d) Vs_[(j)*64 + (d)]
    #define SSI(q,j) Ss_[(q)*65 + (j)]

    int t = threadIdx.x;
    int b = blockIdx.z, h = blockIdx.y;
    int f0 = b * NN + blockIdx.x * 32;

    for (int i = t; i < 32*64; i += 256) {
        int r = i >> 6, c = i & 63;
        QSI(r, c) = Qbuf[(size_t)(f0 + r)*DIN + h*HD + c];
    }
    if (t < 32) { mrow[t] = -INFINITY; lrow[t] = 0.0f; }
    float o[8] = {};
    int qown = t >> 3, d0 = (t & 7) * 8;
    int qg = t >> 4, jg = t & 15;
    __syncthreads();

    for (int j0 = 0; j0 < m; j0 += 64) {
        for (int i = t; i < 64*64; i += 256) {
            int r = i >> 6, c = i & 63;
            size_t base = ((size_t)b*m + j0 + r)*DIN + h*HD + c;
            KSI(c, r) = Ksrc[base];
            VSI(r, c) = Vsrc[base];
        }
        __syncthreads();
        float acc[2][4] = {};
        #pragma unroll 16
        for (int d = 0; d < 64; d++) {
            float a0 = QSI(qg*2+0, d), a1 = QSI(qg*2+1, d);
            float b0 = KSI(d, jg*4+0), b1 = KSI(d, jg*4+1);
            float b2 = KSI(d, jg*4+2), b3 = KSI(d, jg*4+3);
            acc[0][0] += a0*b0; acc[0][1] += a0*b1; acc[0][2] += a0*b2; acc[0][3] += a0*b3;
            acc[1][0] += a1*b0; acc[1][1] += a1*b1; acc[1][2] += a1*b2; acc[1][3] += a1*b3;
        }
        #pragma unroll
        for (int i = 0; i < 2; i++)
            #pragma unroll
            for (int j = 0; j < 4; j++)
                SSI(qg*2+i, jg*4+j) = acc[i][j] * SCALE;
        __syncthreads();
        if (t < 32) {
            float mo = mrow[t];
            float mc = mo;
            for (int j = 0; j < 64; j++) mc = fmaxf(mc, SSI(t, j));
            float fscale = __expf(mo - mc);
            float s = 0.0f;
            for (int j = 0; j < 64; j++) {
                float e = __expf(SSI(t, j) - mc);
                SSI(t, j) = e; s += e;
            }
            lrow[t] = lrow[t] * fscale + s;
            mrow[t] = mc;
            fac[t]  = fscale;
        }
        __syncthreads();
        float fq = fac[qown];
        #pragma unroll
        for (int u = 0; u < 8; u++) o[u] *= fq;
        for (int j = 0; j < 64; j++) {
            float p = SSI(qown, j);
            #pragma unroll
            for (int u = 0; u < 8; u++) o[u] += p * VSI(j, d0 + u);
        }
        __syncthreads();
    }
    float inv = 1.0f / lrow[qown];
    #pragma unroll
    for (int u = 0; u < 8; u++)
        Obuf[(size_t)(f0 + qown)*DOUT + h*HD + d0 + u] = o[u] * inv;
    #undef QSI
    #undef KSI
    #undef VSI
    #undef SSI
}

// ---------------------------- gate combine -----------------------------------
__global__ void combine_kernel(float* __restrict__ out)
{
    int e = blockIdx.x * 256 + threadIdx.x;  // < 2048*1024
    float w = g_w[e];
    out[e] = w * g_c1[e] + (1.0f - w) * g_c2[e];
}

// ------------------------------- launch --------------------------------------
extern "C" void kernel_launch(void* const* d_in, const int* in_sizes, int n_in,
                              void* d_out, int out_size)
{
    const float* x     = (const float*)d_in[0];
    const float* Wq    = (const float*)d_in[1];
    const float* Wk    = (const float*)d_in[2];
    const float* Wv    = (const float*)d_in[3];
    const float* Ww    = (const float*)d_in[4];
    const float* Wo    = (const float*)d_in[5];
    const float* bo    = (const float*)d_in[6];
    const float* kmem0 = (const float*)d_in[7];
    const float* vmem0 = (const float*)d_in[8];
    float* out = (float*)d_out;

    float *q, *k, *v, *w, *ao, *aom, *c1, *c2, *km, *vm;
    cudaGetSymbolAddress((void**)&q,   g_q);
    cudaGetSymbolAddress((void**)&k,   g_k);
    cudaGetSymbolAddress((void**)&v,   g_v);
    cudaGetSymbolAddress((void**)&w,   g_w);
    cudaGetSymbolAddress((void**)&ao,  g_ao);
    cudaGetSymbolAddress((void**)&aom, g_aom);
    cudaGetSymbolAddress((void**)&c1,  g_c1);
    cudaGetSymbolAddress((void**)&c2,  g_c2);
    cudaGetSymbolAddress((void**)&km,  g_km);
    cudaGetSymbolAddress((void**)&vm,  g_vm);

    const int SIMS_SMEM  = (64*68 + 64*65 + 64*65) * 4;            // 50688
    const int FLASH_SMEM = (32*68 + 64*65 + 64*64 + 32*65 + 96)*4; // 50432
    cudaFuncSetAttribute(sims_topk,  cudaFuncAttributeMaxDynamicSharedMemorySize, SIMS_SMEM);
    cudaFuncSetAttribute(flash_attn, cudaFuncAttributeMaxDynamicSharedMemorySize, FLASH_SMEM);

    dim3 gemm_grid(DOUT/64, BNR/64);   // (16, 32)

    // projections
    sgemm_abt<<<gemm_grid, 256>>>(x, Wq, q, BNR, DIN,  DIN, nullptr, 0);
    sgemm_abt<<<gemm_grid, 256>>>(x, Wk, k, BNR, DIN,  DIN, nullptr, 0);
    sgemm_abt<<<gemm_grid, 256>>>(x, Wv, v, BNR, DOUT, DIN, nullptr, 0);
    sgemm_abt<<<gemm_grid, 256>>>(x, Ww, w, BNR, DOUT, DIN, nullptr, 1);

    // local attention (pre-Wo)
    flash_attn<<<dim3(NN/32, H, BB), 256, FLASH_SMEM>>>(q, k, v, ao, NN);

    // exact IP search top-8
    sims_topk<<<dim3(BNR/64, H), 256, SIMS_SMEM>>>(q, k, kmem0);

    // gather retrieved k/v into [b, n*IPQ, 1024]
    gather_kernel<<<(BB*NN*IPQ*DIN)/256, 256>>>(kmem0, vmem0);

    // memory attention (pre-Wo), m = 4096
    flash_attn<<<dim3(NN/32, H, BB), 256, FLASH_SMEM>>>(q, km, vm, aom, NN*IPQ);

    // output projections + bias
    sgemm_abt<<<gemm_grid, 256>>>(ao,  Wo, c1, BNR, DOUT, DOUT, bo, 0);
    sgemm_abt<<<gemm_grid, 256>>>(aom, Wo, c2, BNR, DOUT, DOUT, bo, 0);

    // gated combine
    combine_kernel<<<(BNR*DOUT)/256, 256>>>(out);
}

// round 7
// speedup vs baseline: 1.4032x; 1.4032x over previous
#include <cuda_runtime.h>
#include <cuda_fp16.h>
#include <cstdint>
#include <cstdio>
#include <math.h>

typedef unsigned int u32;

#define H    16
#define HD   64
#define MEMS 32768
#define IPQ  8
#define BB   4
#define NN   512
#define DIN  1024
#define DOUT 1024
#define BNR  (BB*NN)
#define MOLD (MEMS - BNR)
#define SCALE 0.125f

// ------------------------- scratch (device globals) -------------------------
__device__ float g_q  [BNR*DIN];
__device__ float g_k  [BNR*DIN];
__device__ float g_v  [BNR*DOUT];
__device__ float g_w  [BNR*DOUT];
__device__ float g_ao [BNR*DOUT];
__device__ float g_aom[BNR*DOUT];
__device__ float g_c1 [BNR*DOUT];
__device__ float g_c2 [BNR*DOUT];
__device__ float g_km [(size_t)BB*(NN*IPQ)*DIN];
__device__ float g_vm [(size_t)BB*(NN*IPQ)*DOUT];
__device__ int   g_idx[H*BNR*IPQ];

// ------------------------- helpers -------------------------
__device__ __forceinline__ u32 smem_u32(const void* p) {
    return (u32)__cvta_generic_to_shared(p);
}
__device__ __forceinline__ void ldsm_x4(u32 &r0, u32 &r1, u32 &r2, u32 &r3, u32 addr) {
    asm volatile("ldmatrix.sync.aligned.m8n8.x4.shared.b16 {%0,%1,%2,%3}, [%4];"
        : "=r"(r0), "=r"(r1), "=r"(r2), "=r"(r3) : "r"(addr));
}
__device__ __forceinline__ void ldsm_x2(u32 &r0, u32 &r1, u32 addr) {
    asm volatile("ldmatrix.sync.aligned.m8n8.x2.shared.b16 {%0,%1}, [%2];"
        : "=r"(r0), "=r"(r1) : "r"(addr));
}
__device__ __forceinline__ void mma_f16(float* c, u32 a0, u32 a1, u32 a2, u32 a3,
                                        u32 b0, u32 b1) {
    asm volatile("mma.sync.aligned.m16n8k16.row.col.f32.f16.f16.f32 "
        "{%0,%1,%2,%3}, {%4,%5,%6,%7}, {%8,%9}, {%0,%1,%2,%3};"
        : "+f"(c[0]), "+f"(c[1]), "+f"(c[2]), "+f"(c[3])
        : "r"(a0), "r"(a1), "r"(a2), "r"(a3), "r"(b0), "r"(b1));
}

// ------------------------- SGEMM: C = A * B^T ------------------------
// A [M,K] rm, B [N,K] rm, C [M,N]. 128x128 tiles, 256 thr, 8x8 per thread.
__global__ void __launch_bounds__(256, 2)
sgemm_abt(const float* __restrict__ A, const float* __restrict__ B,
          float* __restrict__ C, int M, int N, int K,
          const float* __restrict__ bias, int do_sigmoid)
{
    __shared__ float As[16][132];
    __shared__ float Bs[16][132];
    int t  = threadIdx.x;
    int tx = t & 15, ty = t >> 4;
    int row0 = blockIdx.y * 128, col0 = blockIdx.x * 128;
    float acc[8][8] = {};

    for (int k0 = 0; k0 < K; k0 += 16) {
        #pragma unroll
        for (int vv = 0; vv < 2; vv++) {
            int lin = t + vv * 256;
            int r   = lin >> 2;
            int kq  = (lin & 3) * 4;
            float4 av = *(const float4*)&A[(size_t)(row0 + r) * K + k0 + kq];
            As[kq+0][r] = av.x; As[kq+1][r] = av.y; As[kq+2][r] = av.z; As[kq+3][r] = av.w;
            float4 bv = *(const float4*)&B[(size_t)(col0 + r) * K + k0 + kq];
            Bs[kq+0][r] = bv.x; Bs[kq+1][r] = bv.y; Bs[kq+2][r] = bv.z; Bs[kq+3][r] = bv.w;
        }
        __syncthreads();
        #pragma unroll
        for (int kk = 0; kk < 16; kk++) {
            float a[8], b[8];
            *(float4*)&a[0] = *(const float4*)&As[kk][ty*8];
            *(float4*)&a[4] = *(const float4*)&As[kk][ty*8 + 4];
            *(float4*)&b[0] = *(const float4*)&Bs[kk][tx*8];
            *(float4*)&b[4] = *(const float4*)&Bs[kk][tx*8 + 4];
            #pragma unroll
            for (int i = 0; i < 8; i++) {
                #pragma unroll
                for (int j = 0; j < 8; j++) {
                    acc[i][j] += a[i] * b[j];
                }
            }
        }
        __syncthreads();
    }
    #pragma unroll
    for (int i = 0; i < 8; i++) {
        int r = row0 + ty*8 + i;
        #pragma unroll
        for (int j = 0; j < 8; j++) {
            int c = col0 + tx*8 + j;
            float v = acc[i][j];
            if (bias) v += bias[c];
            if (do_sigmoid) v = 1.0f / (1.0f + __expf(-v));
            C[(size_t)r * N + c] = v;
        }
    }
}

// ------------------------- top-8 push helper -------------------------
__device__ __forceinline__ void tk_push(float s, int id, float* tv, int* ti,
                                        float &tmin, int &tpos) {
    if (s > tmin) {
        tv[tpos] = s; ti[tpos] = id;
        tmin = tv[0]; tpos = 0;
        #pragma unroll
        for (int p = 1; p < 8; p++) {
            if (tv[p] < tmin) { tmin = tv[p]; tpos = p; }
        }
    }
}

// --------------- sims + top-8 via fp16 split HMMA ---------------------------
// sim = q_hi*k_hi + q_hi*k_lo + q_lo*k_hi  (residual ~2^-22 -> exact ranking)
// grid (32, 16): blockIdx.x = 64-query tile, blockIdx.y = head. 256 thr, 8 warps.
// Per 128-key tile: warp w -> q-strip 16*(w>>1), key-half (w&1)*64.
__global__ void __launch_bounds__(256, 2)
sims_topk(const float* __restrict__ Qbuf, const float* __restrict__ Kbuf,
          const float* __restrict__ kmem0)
{
    extern __shared__ char smraw[];
    __half* Qh = (__half*)smraw;              // [64][72] hi
    __half* Ql = Qh + 64*72;                  // [64][72] lo
    __half* Kh = Ql + 64*72;                  // [128][72] hi
    __half* Kl = Kh + 128*72;                 // [128][72] lo
    float* Ss = (float*)(smraw + (2*64*72 + 2*128*72)*2);   // [64][132]

    const u32 QLO_OFF = 64*72*2;   // bytes Qh -> Ql
    const u32 KLO_OFF = 128*72*2;  // bytes Kh -> Kl

    int t = threadIdx.x;
    int h = blockIdx.y;
    int q0 = blockIdx.x * 64;
    int lane = t & 31, warp = t >> 5;
    int gid = lane >> 2, tig = lane & 3;

    // load Q once -> fp16 hi/lo
    for (int i = t; i < 64*64; i += 256) {
        int r = i >> 6, c = i & 63;
        float val = Qbuf[(size_t)(q0 + r)*DIN + h*HD + c];
        __half hi = __float2half_rn(val);
        Qh[r*72 + c] = hi;
        Ql[r*72 + c] = __float2half_rn(val - __half2float(hi));
    }

    float tv[8]; int ti[8];
    #pragma unroll
    for (int p = 0; p < 8; p++) { tv[p] = -INFINITY; ti[p] = 0; }
    float tmin = -INFINITY; int tpos = 0;

    int q0w = (warp >> 1) * 16;
    int kh0 = (warp & 1) * 64;

    u32 a_base = smem_u32(&Qh[(q0w + (lane & 15))*72 + ((lane >> 4) & 1)*8]);
    u32 b_base = smem_u32(&Kh[(kh0 + (lane & 7))*72 + ((lane >> 3) & 1)*8]);

    int qrow = t & 63, seg = t >> 6;

    for (int tile = 0; tile < MEMS/128; tile++) {
        int j0 = tile * 128;
        // load K tile (128 keys x 64 dims) -> fp16 hi/lo
        for (int i = t; i < 128*64; i += 256) {
            int r = i >> 6, c = i & 63;
            int gk = j0 + r;
            float val = (gk < MOLD)
                ? kmem0[((size_t)h*MEMS + gk + BNR)*HD + c]
                : Kbuf[(size_t)(gk - MOLD)*DIN + h*HD + c];
            __half hi = __float2half_rn(val);
            Kh[r*72 + c] = hi;
            Kl[r*72 + c] = __float2half_rn(val - __half2float(hi));
        }
        __syncthreads();

        float c8[8][4] = {};
        #pragma unroll
        for (int ks = 0; ks < 4; ks++) {
            u32 ah0, ah1, ah2, ah3, al0, al1, al2, al3;
            ldsm_x4(ah0, ah1, ah2, ah3, a_base + ks*32);
            ldsm_x4(al0, al1, al2, al3, a_base + QLO_OFF + ks*32);
            #pragma unroll
            for (int j = 0; j < 8; j++) {
                u32 bh0, bh1, bl0, bl1;
                u32 boff = b_base + (u32)j*(8*72*2) + ks*32;
                ldsm_x2(bh0, bh1, boff);
                ldsm_x2(bl0, bl1, boff + KLO_OFF);
                mma_f16(c8[j], ah0, ah1, ah2, ah3, bh0, bh1);  // hi*hi
                mma_f16(c8[j], ah0, ah1, ah2, ah3, bl0, bl1);  // hi*lo
                mma_f16(c8[j], al0, al1, al2, al3, bh0, bh1);  // lo*hi
            }
        }
        #pragma unroll
        for (int j = 0; j < 8; j++) {
            int col = kh0 + 8*j + 2*tig;
            Ss[(q0w + gid    )*132 + col    ] = c8[j][0];
            Ss[(q0w + gid    )*132 + col + 1] = c8[j][1];
            Ss[(q0w + gid + 8)*132 + col    ] = c8[j][2];
            Ss[(q0w + gid + 8)*132 + col + 1] = c8[j][3];
        }
        __syncthreads();

        // scan: thread owns row (t&63), 32-key segment seg
        const float4* srow = (const float4*)&Ss[qrow*132 + seg*32];
        int cb = j0 + seg*32;
        #pragma unroll
        for (int vv = 0; vv < 8; vv++) {
            float4 s4 = srow[vv];
            tk_push(s4.x, cb + vv*4 + 0, tv, ti, tmin, tpos);
            tk_push(s4.y, cb + vv*4 + 1, tv, ti, tmin, tpos);
            tk_push(s4.z, cb + vv*4 + 2, tv, ti, tmin, tpos);
            tk_push(s4.w, cb + vv*4 + 3, tv, ti, tmin, tpos);
        }
        // next K-load writes only Kh/Kl (not read by scan); Ss rewrite is
        // fenced by the post-load __syncthreads().
    }
    __syncthreads();

    // merge 4 partial lists per query row
    float* cval = Ss;
    int*   cidx = (int*)(Ss + 2048);
    #pragma unroll
    for (int p = 0; p < 8; p++) { cval[t*8 + p] = tv[p]; cidx[t*8 + p] = ti[p]; }
    __syncthreads();
    if (t < 64) {
        float fv[8]; int fi[8]; float fmin = -INFINITY; int fpos = 0;
        #pragma unroll
        for (int p = 0; p < 8; p++) { fv[p] = -INFINITY; fi[p] = 0; }
        for (int g = 0; g < 4; g++) {
            int src = t + g*64;
            #pragma unroll
            for (int p = 0; p < 8; p++) {
                tk_push(cval[src*8 + p], cidx[src*8 + p], fv, fi, fmin, fpos);
            }
        }
        #pragma unroll
        for (int p = 0; p < 8; p++) {
            g_idx[((size_t)h*BNR + q0 + t)*IPQ + p] = fi[p];
        }
    }
}

// --------------------- gather k_m / v_m from idx -----------------------------
__global__ void gather_kernel(const float* __restrict__ kmem0, const float* __restrict__ vmem0)
{
    int e = blockIdx.x * 256 + threadIdx.x;
    int c  = e & 1023;
    int m2 = (e >> 10) & 4095;
    int b  = e >> 22;
    int h = c >> 6, d = c & 63;
    int nq = m2 >> 3, ip = m2 & 7;
    int f = b * NN + nq;
    int row = g_idx[((size_t)h*BNR + f)*IPQ + ip];
    float kv, vv;
    if (row < MOLD) {
        size_t base = ((size_t)h*MEMS + row + BNR)*HD + d;
        kv = kmem0[base]; vv = vmem0[base];
    } else {
        int fl = row - MOLD;
        size_t base = (size_t)fl*DIN + h*HD + d;
        kv = g_k[base]; vv = g_v[base];
    }
    g_km[e] = kv;
    g_vm[e] = vv;
}

// ------------------- flash attention (shared for a, a_m) ---------------------
__global__ void flash_attn(const float* __restrict__ Qbuf, const float* __restrict__ Ksrc,
                           const float* __restrict__ Vsrc, float* __restrict__ Obuf, int m)
{
    extern __shared__ float sm[];
    float* Qs_ = sm;                     // [32][68]
    float* Ks_ = Qs_ + 32*68;            // [64][65] d-major
    float* Vs_ = Ks_ + 64*65;            // [64][64] j-major
    float* Ss_ = Vs_ + 64*64;            // [32][65]
    float* mrow = Ss_ + 32*65;
    float* lrow = mrow + 32;
    float* fac  = lrow + 32;

    int t = threadIdx.x;
    int b = blockIdx.z, h = blockIdx.y;
    int f0 = b * NN + blockIdx.x * 32;

    for (int i = t; i < 32*64; i += 256) {
        int r = i >> 6, c = i & 63;
        Qs_[r*68 + c] = Qbuf[(size_t)(f0 + r)*DIN + h*HD + c];
    }
    if (t < 32) { mrow[t] = -INFINITY; lrow[t] = 0.0f; }
    float o[8] = {};
    int qown = t >> 3, d0 = (t & 7) * 8;
    int qg = t >> 4, jg = t & 15;
    __syncthreads();

    for (int j0 = 0; j0 < m; j0 += 64) {
        for (int i = t; i < 64*64; i += 256) {
            int r = i >> 6, c = i & 63;
            size_t base = ((size_t)b*m + j0 + r)*DIN + h*HD + c;
            Ks_[c*65 + r] = Ksrc[base];
            Vs_[r*64 + c] = Vsrc[base];
        }
        __syncthreads();
        float acc[2][4] = {};
        #pragma unroll 16
        for (int d = 0; d < 64; d++) {
            float a0 = Qs_[(qg*2+0)*68 + d], a1 = Qs_[(qg*2+1)*68 + d];
            float b0 = Ks_[d*65 + jg*4+0], b1 = Ks_[d*65 + jg*4+1];
            float b2 = Ks_[d*65 + jg*4+2], b3 = Ks_[d*65 + jg*4+3];
            acc[0][0] += a0*b0; acc[0][1] += a0*b1; acc[0][2] += a0*b2; acc[0][3] += a0*b3;
            acc[1][0] += a1*b0; acc[1][1] += a1*b1; acc[1][2] += a1*b2; acc[1][3] += a1*b3;
        }
        #pragma unroll
        for (int i = 0; i < 2; i++) {
            #pragma unroll
            for (int j = 0; j < 4; j++) {
                Ss_[(qg*2+i)*65 + jg*4+j] = acc[i][j] * SCALE;
            }
        }
        __syncthreads();
        if (t < 32) {
            float mo = mrow[t];
            float mc = mo;
            for (int j = 0; j < 64; j++) mc = fmaxf(mc, Ss_[t*65 + j]);
            float fscale = __expf(mo - mc);
            float s = 0.0f;
            for (int j = 0; j < 64; j++) {
                float e = __expf(Ss_[t*65 + j] - mc);
                Ss_[t*65 + j] = e; s += e;
            }
            lrow[t] = lrow[t] * fscale + s;
            mrow[t] = mc;
            fac[t]  = fscale;
        }
        __syncthreads();
        float fq = fac[qown];
        #pragma unroll
        for (int u = 0; u < 8; u++) o[u] *= fq;
        for (int j = 0; j < 64; j++) {
            float p = Ss_[qown*65 + j];
            #pragma unroll
            for (int u = 0; u < 8; u++) o[u] += p * Vs_[j*64 + d0 + u];
        }
        __syncthreads();
    }
    float inv = 1.0f / lrow[qown];
    #pragma unroll
    for (int u = 0; u < 8; u++) {
        Obuf[(size_t)(f0 + qown)*DOUT + h*HD + d0 + u] = o[u] * inv;
    }
}

// ---------------------------- gate combine -----------------------------------
__global__ void combine_kernel(float* __restrict__ out)
{
    int e = blockIdx.x * 256 + threadIdx.x;
    float w = g_w[e];
    out[e] = w * g_c1[e] + (1.0f - w) * g_c2[e];
}

// ------------------------------- launch --------------------------------------
extern "C" void kernel_launch(void* const* d_in, const int* in_sizes, int n_in,
                              void* d_out, int out_size)
{
    const float* x     = (const float*)d_in[0];
    const float* Wq    = (const float*)d_in[1];
    const float* Wk    = (const float*)d_in[2];
    const float* Wv    = (const float*)d_in[3];
    const float* Ww    = (const float*)d_in[4];
    const float* Wo    = (const float*)d_in[5];
    const float* bo    = (const float*)d_in[6];
    const float* kmem0 = (const float*)d_in[7];
    const float* vmem0 = (const float*)d_in[8];
    float* out = (float*)d_out;

    float *q, *k, *v, *w, *ao, *aom, *c1, *c2, *km, *vm;
    cudaGetSymbolAddress((void**)&q,   g_q);
    cudaGetSymbolAddress((void**)&k,   g_k);
    cudaGetSymbolAddress((void**)&v,   g_v);
    cudaGetSymbolAddress((void**)&w,   g_w);
    cudaGetSymbolAddress((void**)&ao,  g_ao);
    cudaGetSymbolAddress((void**)&aom, g_aom);
    cudaGetSymbolAddress((void**)&c1,  g_c1);
    cudaGetSymbolAddress((void**)&c2,  g_c2);
    cudaGetSymbolAddress((void**)&km,  g_km);
    cudaGetSymbolAddress((void**)&vm,  g_vm);

    const int SIMS_SMEM  = (2*64*72 + 2*128*72)*2 + 64*132*4;   // 89088
    const int FLASH_SMEM = (32*68 + 64*65 + 64*64 + 32*65 + 96)*4;
    cudaFuncSetAttribute(sims_topk,  cudaFuncAttributeMaxDynamicSharedMemorySize, SIMS_SMEM);
    cudaFuncSetAttribute(flash_attn, cudaFuncAttributeMaxDynamicSharedMemorySize, FLASH_SMEM);

    dim3 gemm_grid(DOUT/128, BNR/128);

    sgemm_abt<<<gemm_grid, 256>>>(x, Wq, q, BNR, DIN,  DIN, 0, 0);
    sgemm_abt<<<gemm_grid, 256>>>(x, Wk, k, BNR, DIN,  DIN, 0, 0);
    sgemm_abt<<<gemm_grid, 256>>>(x, Wv, v, BNR, DOUT, DIN, 0, 0);
    sgemm_abt<<<gemm_grid, 256>>>(x, Ww, w, BNR, DOUT, DIN, 0, 1);

    flash_attn<<<dim3(NN/32, H, BB), 256, FLASH_SMEM>>>(q, k, v, ao, NN);

    sims_topk<<<dim3(BNR/64, H), 256, SIMS_SMEM>>>(q, k, kmem0);

    gather_kernel<<<(BB*NN*IPQ*DIN)/256, 256>>>(kmem0, vmem0);

    flash_attn<<<dim3(NN/32, H, BB), 256, FLASH_SMEM>>>(q, km, vm, aom, NN*IPQ);

    sgemm_abt<<<gemm_grid, 256>>>(ao,  Wo, c1, BNR, DOUT, DOUT, bo, 0);
    sgemm_abt<<<gemm_grid, 256>>>(aom, Wo, c2, BNR, DOUT, DOUT, bo, 0);

    combine_kernel<<<(BNR*DOUT)/256, 256>>>(out);
}

// round 8
// speedup vs baseline: 1.6100x; 1.1474x over previous
#include <cuda_runtime.h>
#include <cuda_fp16.h>
#include <cstdint>
#include <cstdio>
#include <math.h>

typedef unsigned int u32;

#define H    16
#define HD   64
#define MEMS 32768
#define IPQ  8
#define BB   4
#define NN   512
#define DIN  1024
#define DOUT 1024
#define BNR  (BB*NN)
#define MOLD (MEMS - BNR)
#define SCALE 0.125f

// ------------------------- scratch (device globals) -------------------------
__device__ float g_q  [BNR*DIN];
__device__ float g_k  [BNR*DIN];
__device__ float g_v  [BNR*DOUT];
__device__ float g_w  [BNR*DOUT];
__device__ float g_ao [BNR*DOUT];
__device__ float g_aom[BNR*DOUT];
__device__ float g_c1 [BNR*DOUT];
__device__ float g_c2 [BNR*DOUT];
__device__ float g_km [(size_t)BB*(NN*IPQ)*DIN];
__device__ float g_vm [(size_t)BB*(NN*IPQ)*DOUT];
__device__ int   g_idx[H*BNR*IPQ];
// fp16 split planes, head-major
__device__ __half g_qhi[(size_t)H*BNR*HD];
__device__ __half g_qlo[(size_t)H*BNR*HD];
__device__ __half g_khi[(size_t)H*MEMS*HD];
__device__ __half g_klo[(size_t)H*MEMS*HD];

// ------------------------- helpers -------------------------
__device__ __forceinline__ u32 smem_u32(const void* p) {
    return (u32)__cvta_generic_to_shared(p);
}
__device__ __forceinline__ void ldsm_x4(u32 &r0, u32 &r1, u32 &r2, u32 &r3, u32 addr) {
    asm volatile("ldmatrix.sync.aligned.m8n8.x4.shared.b16 {%0,%1,%2,%3}, [%4];"
        : "=r"(r0), "=r"(r1), "=r"(r2), "=r"(r3) : "r"(addr));
}
__device__ __forceinline__ void ldsm_x2(u32 &r0, u32 &r1, u32 addr) {
    asm volatile("ldmatrix.sync.aligned.m8n8.x2.shared.b16 {%0,%1}, [%2];"
        : "=r"(r0), "=r"(r1) : "r"(addr));
}
__device__ __forceinline__ void mma_f16(float* c, u32 a0, u32 a1, u32 a2, u32 a3,
                                        u32 b0, u32 b1) {
    asm volatile("mma.sync.aligned.m16n8k16.row.col.f32.f16.f16.f32 "
        "{%0,%1,%2,%3}, {%4,%5,%6,%7}, {%8,%9}, {%0,%1,%2,%3};"
        : "+f"(c[0]), "+f"(c[1]), "+f"(c[2]), "+f"(c[3])
        : "r"(a0), "r"(a1), "r"(a2), "r"(a3), "r"(b0), "r"(b1));
}

// ------------------------- SGEMM: C = A * B^T ------------------------
__global__ void __launch_bounds__(256, 2)
sgemm_abt(const float* __restrict__ A, const float* __restrict__ B,
          float* __restrict__ C, int M, int N, int K,
          const float* __restrict__ bias, int do_sigmoid)
{
    __shared__ float As[16][132];
    __shared__ float Bs[16][132];
    int t  = threadIdx.x;
    int tx = t & 15, ty = t >> 4;
    int row0 = blockIdx.y * 128, col0 = blockIdx.x * 128;
    float acc[8][8] = {};

    for (int k0 = 0; k0 < K; k0 += 16) {
        #pragma unroll
        for (int vv = 0; vv < 2; vv++) {
            int lin = t + vv * 256;
            int r   = lin >> 2;
            int kq  = (lin & 3) * 4;
            float4 av = *(const float4*)&A[(size_t)(row0 + r) * K + k0 + kq];
            As[kq+0][r] = av.x; As[kq+1][r] = av.y; As[kq+2][r] = av.z; As[kq+3][r] = av.w;
            float4 bv = *(const float4*)&B[(size_t)(col0 + r) * K + k0 + kq];
            Bs[kq+0][r] = bv.x; Bs[kq+1][r] = bv.y; Bs[kq+2][r] = bv.z; Bs[kq+3][r] = bv.w;
        }
        __syncthreads();
        #pragma unroll
        for (int kk = 0; kk < 16; kk++) {
            float a[8], b[8];
            *(float4*)&a[0] = *(const float4*)&As[kk][ty*8];
            *(float4*)&a[4] = *(const float4*)&As[kk][ty*8 + 4];
            *(float4*)&b[0] = *(const float4*)&Bs[kk][tx*8];
            *(float4*)&b[4] = *(const float4*)&Bs[kk][tx*8 + 4];
            #pragma unroll
            for (int i = 0; i < 8; i++) {
                #pragma unroll
                for (int j = 0; j < 8; j++) {
                    acc[i][j] += a[i] * b[j];
                }
            }
        }
        __syncthreads();
    }
    #pragma unroll
    for (int i = 0; i < 8; i++) {
        int r = row0 + ty*8 + i;
        #pragma unroll
        for (int j = 0; j < 8; j++) {
            int c = col0 + tx*8 + j;
            float v = acc[i][j];
            if (bias) v += bias[c];
            if (do_sigmoid) v = 1.0f / (1.0f + __expf(-v));
            C[(size_t)r * N + c] = v;
        }
    }
}

// ------------------- fp16 split precompute ----------------------------
__global__ void convert_k(const float* __restrict__ kmem0)
{
    int e = blockIdx.x * 256 + threadIdx.x;   // < H*MEMS*HD = 2^25
    int d = e & 63;
    int j = (e >> 6) & (MEMS - 1);
    int h = e >> 21;
    float val = (j < MOLD)
        ? kmem0[((size_t)h*MEMS + j + BNR)*HD + d]
        : g_k[(size_t)(j - MOLD)*DIN + h*HD + d];
    __half hi = __float2half_rn(val);
    g_khi[e] = hi;
    g_klo[e] = __float2half_rn(val - __half2float(hi));
}

__global__ void convert_q()
{
    int e = blockIdx.x * 256 + threadIdx.x;   // < H*BNR*HD = 2^21
    int d = e & 63;
    int r = (e >> 6) & (BNR - 1);
    int h = e >> 17;
    float val = g_q[(size_t)r*DIN + h*HD + d];
    __half hi = __float2half_rn(val);
    g_qhi[e] = hi;
    g_qlo[e] = __float2half_rn(val - __half2float(hi));
}

// ------------------------- top-8 push helper -------------------------
__device__ __forceinline__ void tk_push(float s, int id, float* tv, int* ti,
                                        float &tmin, int &tpos) {
    if (s > tmin) {
        tv[tpos] = s; ti[tpos] = id;
        tmin = tv[0]; tpos = 0;
        #pragma unroll
        for (int p = 1; p < 8; p++) {
            if (tv[p] < tmin) { tmin = tv[p]; tpos = p; }
        }
    }
}

// --------------- sims + top-8 via fp16 split HMMA ---------------------------
// sim = q_hi*k_hi + q_hi*k_lo + q_lo*k_hi  (residual ~2^-22 -> exact ranking)
__global__ void __launch_bounds__(256, 2)
sims_topk()
{
    extern __shared__ char smraw[];
    __half* Qh = (__half*)smraw;              // [64][72] hi
    __half* Ql = Qh + 64*72;                  // [64][72] lo
    __half* Kh = Ql + 64*72;                  // [128][72] hi
    __half* Kl = Kh + 128*72;                 // [128][72] lo
    float* Ss = (float*)(smraw + (2*64*72 + 2*128*72)*2);   // [64][132]

    const u32 QLO_OFF = 64*72*2;
    const u32 KLO_OFF = 128*72*2;

    int t = threadIdx.x;
    int h = blockIdx.y;
    int q0 = blockIdx.x * 64;
    int lane = t & 31, warp = t >> 5;
    int gid = lane >> 2, tig = lane & 3;

    // load Q planes (vectorized, no conversion)
    {
        int r = t >> 2, c0 = (t & 3) * 16;
        size_t src = ((size_t)h*BNR + q0 + r)*HD + c0;
        *(uint4*)&Qh[r*72 + c0    ] = *(const uint4*)&g_qhi[src];
        *(uint4*)&Qh[r*72 + c0 + 8] = *(const uint4*)&g_qhi[src + 8];
        *(uint4*)&Ql[r*72 + c0    ] = *(const uint4*)&g_qlo[src];
        *(uint4*)&Ql[r*72 + c0 + 8] = *(const uint4*)&g_qlo[src + 8];
    }

    float tv[8]; int ti[8];
    #pragma unroll
    for (int p = 0; p < 8; p++) { tv[p] = -INFINITY; ti[p] = 0; }
    float tmin = -INFINITY; int tpos = 0;

    int q0w = (warp >> 1) * 16;
    int kh0 = (warp & 1) * 64;

    u32 a_base = smem_u32(&Qh[(q0w + (lane & 15))*72 + ((lane >> 4) & 1)*8]);
    u32 b_base = smem_u32(&Kh[(kh0 + (lane & 7))*72 + ((lane >> 3) & 1)*8]);

    int qrow = t & 63, seg = t >> 6;
    int kr = t >> 1, kc0 = (t & 1) * 32;

    for (int tile = 0; tile < MEMS/128; tile++) {
        int j0 = tile * 128;
        // load K tile planes (vectorized)
        {
            size_t src = ((size_t)h*MEMS + j0 + kr)*HD + kc0;
            #pragma unroll
            for (int uu = 0; uu < 4; uu++) {
                *(uint4*)&Kh[kr*72 + kc0 + uu*8] = *(const uint4*)&g_khi[src + uu*8];
            }
            #pragma unroll
            for (int uu = 0; uu < 4; uu++) {
                *(uint4*)&Kl[kr*72 + kc0 + uu*8] = *(const uint4*)&g_klo[src + uu*8];
            }
        }
        __syncthreads();

        float c8[8][4] = {};
        #pragma unroll
        for (int ks = 0; ks < 4; ks++) {
            u32 ah0, ah1, ah2, ah3, al0, al1, al2, al3;
            ldsm_x4(ah0, ah1, ah2, ah3, a_base + ks*32);
            ldsm_x4(al0, al1, al2, al3, a_base + QLO_OFF + ks*32);
            #pragma unroll
            for (int j = 0; j < 8; j++) {
                u32 bh0, bh1, bl0, bl1;
                u32 boff = b_base + (u32)j*(8*72*2) + ks*32;
                ldsm_x2(bh0, bh1, boff);
                ldsm_x2(bl0, bl1, boff + KLO_OFF);
                mma_f16(c8[j], ah0, ah1, ah2, ah3, bh0, bh1);
                mma_f16(c8[j], ah0, ah1, ah2, ah3, bl0, bl1);
                mma_f16(c8[j], al0, al1, al2, al3, bh0, bh1);
            }
        }
        #pragma unroll
        for (int j = 0; j < 8; j++) {
            int col = kh0 + 8*j + 2*tig;
            *(float2*)&Ss[(q0w + gid    )*132 + col] = make_float2(c8[j][0], c8[j][1]);
            *(float2*)&Ss[(q0w + gid + 8)*132 + col] = make_float2(c8[j][2], c8[j][3]);
        }
        __syncthreads();

        // scan with max4 prefilter: thread owns row (t&63), 32-key segment seg
        const float4* srow = (const float4*)&Ss[qrow*132 + seg*32];
        int cb = j0 + seg*32;
        #pragma unroll
        for (int vv = 0; vv < 8; vv++) {
            float4 s4 = srow[vv];
            float m4 = fmaxf(fmaxf(s4.x, s4.y), fmaxf(s4.z, s4.w));
            if (m4 > tmin) {
                tk_push(s4.x, cb + vv*4 + 0, tv, ti, tmin, tpos);
                tk_push(s4.y, cb + vv*4 + 1, tv, ti, tmin, tpos);
                tk_push(s4.z, cb + vv*4 + 2, tv, ti, tmin, tpos);
                tk_push(s4.w, cb + vv*4 + 3, tv, ti, tmin, tpos);
            }
        }
    }
    __syncthreads();

    // merge 4 partial lists per query row
    float* cval = Ss;
    int*   cidx = (int*)(Ss + 2048);
    #pragma unroll
    for (int p = 0; p < 8; p++) { cval[t*8 + p] = tv[p]; cidx[t*8 + p] = ti[p]; }
    __syncthreads();
    if (t < 64) {
        float fv[8]; int fi[8]; float fmin = -INFINITY; int fpos = 0;
        #pragma unroll
        for (int p = 0; p < 8; p++) { fv[p] = -INFINITY; fi[p] = 0; }
        for (int g = 0; g < 4; g++) {
            int src = t + g*64;
            #pragma unroll
            for (int p = 0; p < 8; p++) {
                tk_push(cval[src*8 + p], cidx[src*8 + p], fv, fi, fmin, fpos);
            }
        }
        #pragma unroll
        for (int p = 0; p < 8; p++) {
            g_idx[((size_t)h*BNR + q0 + t)*IPQ + p] = fi[p];
        }
    }
}

// --------------------- gather k_m / v_m from idx -----------------------------
__global__ void gather_kernel(const float* __restrict__ kmem0, const float* __restrict__ vmem0)
{
    int e = blockIdx.x * 256 + threadIdx.x;
    int c  = e & 1023;
    int m2 = (e >> 10) & 4095;
    int b  = e >> 22;
    int h = c >> 6, d = c & 63;
    int nq = m2 >> 3, ip = m2 & 7;
    int f = b * NN + nq;
    int row = g_idx[((size_t)h*BNR + f)*IPQ + ip];
    float kv, vv;
    if (row < MOLD) {
        size_t base = ((size_t)h*MEMS + row + BNR)*HD + d;
        kv = kmem0[base]; vv = vmem0[base];
    } else {
        int fl = row - MOLD;
        size_t base = (size_t)fl*DIN + h*HD + d;
        kv = g_k[base]; vv = g_v[base];
    }
    g_km[e] = kv;
    g_vm[e] = vv;
}

// ------------------- flash attention (shared for a, a_m) ---------------------
// Ks d-major [64 d][68 j], Vs [64 j][68 d], Qs [32 q][68 d], Ss [32][65]
__global__ void flash_attn(const float* __restrict__ Qbuf, const float* __restrict__ Ksrc,
                           const float* __restrict__ Vsrc, float* __restrict__ Obuf, int m)
{
    extern __shared__ float sm[];
    float* Qs_ = sm;                     // 32*68
    float* Ks_ = Qs_ + 32*68;            // 64*68  (d-major)
    float* Vs_ = Ks_ + 64*68;            // 64*68  (j-major)
    float* Ss_ = Vs_ + 64*68;            // 32*65
    float* mrow = Ss_ + 32*65;
    float* lrow = mrow + 32;
    float* fac  = lrow + 32;

    int t = threadIdx.x;
    int b = blockIdx.z, h = blockIdx.y;
    int f0 = b * NN + blockIdx.x * 32;

    {
        int r = t >> 3, c0 = (t & 7) * 8;
        size_t src = (size_t)(f0 + r)*DIN + h*HD + c0;
        *(float4*)&Qs_[r*68 + c0    ] = *(const float4*)&Qbuf[src];
        *(float4*)&Qs_[r*68 + c0 + 4] = *(const float4*)&Qbuf[src + 4];
    }
    if (t < 32) { mrow[t] = -INFINITY; lrow[t] = 0.0f; }
    float o[8] = {};
    int qown = t >> 3, d0 = (t & 7) * 8;
    int qg = t >> 4, jg = t & 15;
    int jrow = t & 63, jc0 = (t >> 6) * 16;
    __syncthreads();

    for (int j0 = 0; j0 < m; j0 += 64) {
        // K transposed into d-major; V row-major
        {
            size_t src = ((size_t)b*m + j0 + jrow)*DIN + h*HD + jc0;
            #pragma unroll
            for (int uu = 0; uu < 4; uu++) {
                float4 kv = *(const float4*)&Ksrc[src + uu*4];
                Ks_[(jc0 + uu*4 + 0)*68 + jrow] = kv.x;
                Ks_[(jc0 + uu*4 + 1)*68 + jrow] = kv.y;
                Ks_[(jc0 + uu*4 + 2)*68 + jrow] = kv.z;
                Ks_[(jc0 + uu*4 + 3)*68 + jrow] = kv.w;
            }
            #pragma unroll
            for (int uu = 0; uu < 4; uu++) {
                *(float4*)&Vs_[jrow*68 + jc0 + uu*4] = *(const float4*)&Vsrc[src + uu*4];
            }
        }
        __syncthreads();

        // QK: per thread 2 q-rows x 4 j-cols, float4 along d
        float acc[2][4] = {};
        #pragma unroll
        for (int d4 = 0; d4 < 16; d4++) {
            float4 a0 = *(const float4*)&Qs_[(qg*2+0)*68 + d4*4];
            float4 a1 = *(const float4*)&Qs_[(qg*2+1)*68 + d4*4];
            float4 bv;
            bv = *(const float4*)&Ks_[(d4*4+0)*68 + jg*4];
            acc[0][0] += a0.x*bv.x; acc[0][1] += a0.x*bv.y; acc[0][2] += a0.x*bv.z; acc[0][3] += a0.x*bv.w;
            acc[1][0] += a1.x*bv.x; acc[1][1] += a1.x*bv.y; acc[1][2] += a1.x*bv.z; acc[1][3] += a1.x*bv.w;
            bv = *(const float4*)&Ks_[(d4*4+1)*68 + jg*4];
            acc[0][0] += a0.y*bv.x; acc[0][1] += a0.y*bv.y; acc[0][2] += a0.y*bv.z; acc[0][3] += a0.y*bv.w;
            acc[1][0] += a1.y*bv.x; acc[1][1] += a1.y*bv.y; acc[1][2] += a1.y*bv.z; acc[1][3] += a1.y*bv.w;
            bv = *(const float4*)&Ks_[(d4*4+2)*68 + jg*4];
            acc[0][0] += a0.z*bv.x; acc[0][1] += a0.z*bv.y; acc[0][2] += a0.z*bv.z; acc[0][3] += a0.z*bv.w;
            acc[1][0] += a1.z*bv.x; acc[1][1] += a1.z*bv.y; acc[1][2] += a1.z*bv.z; acc[1][3] += a1.z*bv.w;
            bv = *(const float4*)&Ks_[(d4*4+3)*68 + jg*4];
            acc[0][0] += a0.w*bv.x; acc[0][1] += a0.w*bv.y; acc[0][2] += a0.w*bv.z; acc[0][3] += a0.w*bv.w;
            acc[1][0] += a1.w*bv.x; acc[1][1] += a1.w*bv.y; acc[1][2] += a1.w*bv.z; acc[1][3] += a1.w*bv.w;
        }
        #pragma unroll
        for (int i = 0; i < 2; i++) {
            #pragma unroll
            for (int j = 0; j < 4; j++) {
                Ss_[(qg*2+i)*65 + jg*4+j] = acc[i][j] * SCALE;
            }
        }
        __syncthreads();
        if (t < 32) {
            float mo = mrow[t];
            float mc = mo;
            for (int j = 0; j < 64; j++) mc = fmaxf(mc, Ss_[t*65 + j]);
            float fscale = __expf(mo - mc);
            float s = 0.0f;
            for (int j = 0; j < 64; j++) {
                float e = __expf(Ss_[t*65 + j] - mc);
                Ss_[t*65 + j] = e; s += e;
            }
            lrow[t] = lrow[t] * fscale + s;
            mrow[t] = mc;
            fac[t]  = fscale;
        }
        __syncthreads();
        float fq = fac[qown];
        #pragma unroll
        for (int u = 0; u < 8; u++) o[u] *= fq;
        for (int j = 0; j < 64; j++) {
            float p = Ss_[qown*65 + j];
            float4 v0 = *(const float4*)&Vs_[j*68 + d0];
            float4 v1 = *(const float4*)&Vs_[j*68 + d0 + 4];
            o[0] += p*v0.x; o[1] += p*v0.y; o[2] += p*v0.z; o[3] += p*v0.w;
            o[4] += p*v1.x; o[5] += p*v1.y; o[6] += p*v1.z; o[7] += p*v1.w;
        }
        __syncthreads();
    }
    float inv = 1.0f / lrow[qown];
    #pragma unroll
    for (int u = 0; u < 8; u++) {
        Obuf[(size_t)(f0 + qown)*DOUT + h*HD + d0 + u] = o[u] * inv;
    }
}

// ---------------------------- gate combine -----------------------------------
__global__ void combine_kernel(float* __restrict__ out)
{
    int e = blockIdx.x * 256 + threadIdx.x;
    float w = g_w[e];
    out[e] = w * g_c1[e] + (1.0f - w) * g_c2[e];
}

// ------------------------------- launch --------------------------------------
extern "C" void kernel_launch(void* const* d_in, const int* in_sizes, int n_in,
                              void* d_out, int out_size)
{
    const float* x     = (const float*)d_in[0];
    const float* Wq    = (const float*)d_in[1];
    const float* Wk    = (const float*)d_in[2];
    const float* Wv    = (const float*)d_in[3];
    const float* Ww    = (const float*)d_in[4];
    const float* Wo    = (const float*)d_in[5];
    const float* bo    = (const float*)d_in[6];
    const float* kmem0 = (const float*)d_in[7];
    const float* vmem0 = (const float*)d_in[8];
    float* out = (float*)d_out;

    float *q, *k, *v, *w, *ao, *aom, *c1, *c2, *km, *vm;
    cudaGetSymbolAddress((void**)&q,   g_q);
    cudaGetSymbolAddress((void**)&k,   g_k);
    cudaGetSymbolAddress((void**)&v,   g_v);
    cudaGetSymbolAddress((void**)&w,   g_w);
    cudaGetSymbolAddress((void**)&ao,  g_ao);
    cudaGetSymbolAddress((void**)&aom, g_aom);
    cudaGetSymbolAddress((void**)&c1,  g_c1);
    cudaGetSymbolAddress((void**)&c2,  g_c2);
    cudaGetSymbolAddress((void**)&km,  g_km);
    cudaGetSymbolAddress((void**)&vm,  g_vm);

    const int SIMS_SMEM  = (2*64*72 + 2*128*72)*2 + 64*132*4;   // 89088
    const int FLASH_SMEM = (32*68 + 64*68 + 64*68 + 32*65 + 96)*4;  // 52608
    cudaFuncSetAttribute(sims_topk,  cudaFuncAttributeMaxDynamicSharedMemorySize, SIMS_SMEM);
    cudaFuncSetAttribute(flash_attn, cudaFuncAttributeMaxDynamicSharedMemorySize, FLASH_SMEM);

    dim3 gemm_grid(DOUT/128, BNR/128);

    sgemm_abt<<<gemm_grid, 256>>>(x, Wq, q, BNR, DIN,  DIN, 0, 0);
    sgemm_abt<<<gemm_grid, 256>>>(x, Wk, k, BNR, DIN,  DIN, 0, 0);
    sgemm_abt<<<gemm_grid, 256>>>(x, Wv, v, BNR, DOUT, DIN, 0, 0);
    sgemm_abt<<<gemm_grid, 256>>>(x, Ww, w, BNR, DOUT, DIN, 0, 1);

    convert_q<<<(H*BNR*HD)/256, 256>>>();
    convert_k<<<(H*MEMS*HD)/256, 256>>>(kmem0);

    flash_attn<<<dim3(NN/32, H, BB), 256, FLASH_SMEM>>>(q, k, v, ao, NN);

    sims_topk<<<dim3(BNR/64, H), 256, SIMS_SMEM>>>();

    gather_kernel<<<(BB*NN*IPQ*DIN)/256, 256>>>(kmem0, vmem0);

    flash_attn<<<dim3(NN/32, H, BB), 256, FLASH_SMEM>>>(q, km, vm, aom, NN*IPQ);

    sgemm_abt<<<gemm_grid, 256>>>(ao,  Wo, c1, BNR, DOUT, DOUT, bo, 0);
    sgemm_abt<<<gemm_grid, 256>>>(aom, Wo, c2, BNR, DOUT, DOUT, bo, 0);

    combine_kernel<<<(BNR*DOUT)/256, 256>>>(out);
}

// round 9
// speedup vs baseline: 1.6669x; 1.0353x over previous
#include <cuda_runtime.h>
#include <cuda_fp16.h>
#include <cstdint>
#include <cstdio>
#include <math.h>

typedef unsigned int u32;

#define H    16
#define HD   64
#define MEMS 32768
#define IPQ  8
#define BB   4
#define NN   512
#define DIN  1024
#define DOUT 1024
#define BNR  (BB*NN)
#define MOLD (MEMS - BNR)
#define SCALE 0.125f

// ------------------------- scratch (device globals) -------------------------
__device__ float g_q  [BNR*DIN];
__device__ float g_k  [BNR*DIN];
__device__ float g_v  [BNR*DOUT];
__device__ float g_w  [BNR*DOUT];
__device__ float g_ao [BNR*DOUT];
__device__ float g_aom[BNR*DOUT];
__device__ float g_c1 [BNR*DOUT];
__device__ float g_c2 [BNR*DOUT];
__device__ float g_km [(size_t)BB*(NN*IPQ)*DIN];
__device__ float g_vm [(size_t)BB*(NN*IPQ)*DOUT];
__device__ int   g_idx[H*BNR*IPQ];
// fp16 split planes, head-major
__device__ __half g_qhi[(size_t)H*BNR*HD];
__device__ __half g_qlo[(size_t)H*BNR*HD];
__device__ __half g_khi[(size_t)H*MEMS*HD];
__device__ __half g_klo[(size_t)H*MEMS*HD];

// ------------------------- helpers -------------------------
__device__ __forceinline__ u32 smem_u32(const void* p) {
    return (u32)__cvta_generic_to_shared(p);
}
__device__ __forceinline__ void ldsm_x4(u32 &r0, u32 &r1, u32 &r2, u32 &r3, u32 addr) {
    asm volatile("ldmatrix.sync.aligned.m8n8.x4.shared.b16 {%0,%1,%2,%3}, [%4];"
        : "=r"(r0), "=r"(r1), "=r"(r2), "=r"(r3) : "r"(addr));
}
__device__ __forceinline__ void ldsm_x2(u32 &r0, u32 &r1, u32 addr) {
    asm volatile("ldmatrix.sync.aligned.m8n8.x2.shared.b16 {%0,%1}, [%2];"
        : "=r"(r0), "=r"(r1) : "r"(addr));
}
__device__ __forceinline__ void mma_f16(float* c, u32 a0, u32 a1, u32 a2, u32 a3,
                                        u32 b0, u32 b1) {
    asm volatile("mma.sync.aligned.m16n8k16.row.col.f32.f16.f16.f32 "
        "{%0,%1,%2,%3}, {%4,%5,%6,%7}, {%8,%9}, {%0,%1,%2,%3};"
        : "+f"(c[0]), "+f"(c[1]), "+f"(c[2]), "+f"(c[3])
        : "r"(a0), "r"(a1), "r"(a2), "r"(a3), "r"(b0), "r"(b1));
}

// ------------------------- SGEMM: C = A * B^T ------------------------
__global__ void __launch_bounds__(256, 2)
sgemm_abt(const float* __restrict__ A, const float* __restrict__ B,
          float* __restrict__ C, int M, int N, int K,
          const float* __restrict__ bias, int do_sigmoid)
{
    __shared__ float As[16][132];
    __shared__ float Bs[16][132];
    int t  = threadIdx.x;
    int tx = t & 15, ty = t >> 4;
    int row0 = blockIdx.y * 128, col0 = blockIdx.x * 128;
    float acc[8][8] = {};

    for (int k0 = 0; k0 < K; k0 += 16) {
        #pragma unroll
        for (int vv = 0; vv < 2; vv++) {
            int lin = t + vv * 256;
            int r   = lin >> 2;
            int kq  = (lin & 3) * 4;
            float4 av = *(const float4*)&A[(size_t)(row0 + r) * K + k0 + kq];
            As[kq+0][r] = av.x; As[kq+1][r] = av.y; As[kq+2][r] = av.z; As[kq+3][r] = av.w;
            float4 bv = *(const float4*)&B[(size_t)(col0 + r) * K + k0 + kq];
            Bs[kq+0][r] = bv.x; Bs[kq+1][r] = bv.y; Bs[kq+2][r] = bv.z; Bs[kq+3][r] = bv.w;
        }
        __syncthreads();
        #pragma unroll
        for (int kk = 0; kk < 16; kk++) {
            float a[8], b[8];
            *(float4*)&a[0] = *(const float4*)&As[kk][ty*8];
            *(float4*)&a[4] = *(const float4*)&As[kk][ty*8 + 4];
            *(float4*)&b[0] = *(const float4*)&Bs[kk][tx*8];
            *(float4*)&b[4] = *(const float4*)&Bs[kk][tx*8 + 4];
            #pragma unroll
            for (int i = 0; i < 8; i++) {
                #pragma unroll
                for (int j = 0; j < 8; j++) {
                    acc[i][j] += a[i] * b[j];
                }
            }
        }
        __syncthreads();
    }
    #pragma unroll
    for (int i = 0; i < 8; i++) {
        int r = row0 + ty*8 + i;
        #pragma unroll
        for (int j = 0; j < 8; j++) {
            int c = col0 + tx*8 + j;
            float v = acc[i][j];
            if (bias) v += bias[c];
            if (do_sigmoid) v = 1.0f / (1.0f + __expf(-v));
            C[(size_t)r * N + c] = v;
        }
    }
}

// ------------------- fp16 split precompute ----------------------------
__global__ void convert_k(const float* __restrict__ kmem0)
{
    int e = blockIdx.x * 256 + threadIdx.x;
    int d = e & 63;
    int j = (e >> 6) & (MEMS - 1);
    int h = e >> 21;
    float val = (j < MOLD)
        ? kmem0[((size_t)h*MEMS + j + BNR)*HD + d]
        : g_k[(size_t)(j - MOLD)*DIN + h*HD + d];
    __half hi = __float2half_rn(val);
    g_khi[e] = hi;
    g_klo[e] = __float2half_rn(val - __half2float(hi));
}

__global__ void convert_q()
{
    int e = blockIdx.x * 256 + threadIdx.x;
    int d = e & 63;
    int r = (e >> 6) & (BNR - 1);
    int h = e >> 17;
    float val = g_q[(size_t)r*DIN + h*HD + d];
    __half hi = __float2half_rn(val);
    g_qhi[e] = hi;
    g_qlo[e] = __float2half_rn(val - __half2float(hi));
}

// ------------------------- top-8 push helper -------------------------
__device__ __forceinline__ void tk_push(float s, int id, float* tv, int* ti,
                                        float &tmin, int &tpos) {
    if (s > tmin) {
        tv[tpos] = s; ti[tpos] = id;
        tmin = tv[0]; tpos = 0;
        #pragma unroll
        for (int p = 1; p < 8; p++) {
            if (tv[p] < tmin) { tmin = tv[p]; tpos = p; }
        }
    }
}

// --------------- sims + top-8 via fp16 split HMMA ---------------------------
__global__ void __launch_bounds__(256, 2)
sims_topk()
{
    extern __shared__ char smraw[];
    __half* Qh = (__half*)smraw;              // [64][72] hi
    __half* Ql = Qh + 64*72;                  // [64][72] lo
    __half* Kh = Ql + 64*72;                  // [128][72] hi
    __half* Kl = Kh + 128*72;                 // [128][72] lo
    float* Ss = (float*)(smraw + (2*64*72 + 2*128*72)*2);   // [64][132]

    const u32 QLO_OFF = 64*72*2;
    const u32 KLO_OFF = 128*72*2;

    int t = threadIdx.x;
    int h = blockIdx.y;
    int q0 = blockIdx.x * 64;
    int lane = t & 31, warp = t >> 5;
    int gid = lane >> 2, tig = lane & 3;

    {
        int r = t >> 2, c0 = (t & 3) * 16;
        size_t src = ((size_t)h*BNR + q0 + r)*HD + c0;
        *(uint4*)&Qh[r*72 + c0    ] = *(const uint4*)&g_qhi[src];
        *(uint4*)&Qh[r*72 + c0 + 8] = *(const uint4*)&g_qhi[src + 8];
        *(uint4*)&Ql[r*72 + c0    ] = *(const uint4*)&g_qlo[src];
        *(uint4*)&Ql[r*72 + c0 + 8] = *(const uint4*)&g_qlo[src + 8];
    }

    float tv[8]; int ti[8];
    #pragma unroll
    for (int p = 0; p < 8; p++) { tv[p] = -INFINITY; ti[p] = 0; }
    float tmin = -INFINITY; int tpos = 0;

    int q0w = (warp >> 1) * 16;
    int kh0 = (warp & 1) * 64;

    u32 a_base = smem_u32(&Qh[(q0w + (lane & 15))*72 + ((lane >> 4) & 1)*8]);
    u32 b_base = smem_u32(&Kh[(kh0 + (lane & 7))*72 + ((lane >> 3) & 1)*8]);

    int qrow = t & 63, seg = t >> 6;
    int kr = t >> 1, kc0 = (t & 1) * 32;

    for (int tile = 0; tile < MEMS/128; tile++) {
        int j0 = tile * 128;
        {
            size_t src = ((size_t)h*MEMS + j0 + kr)*HD + kc0;
            #pragma unroll
            for (int uu = 0; uu < 4; uu++) {
                *(uint4*)&Kh[kr*72 + kc0 + uu*8] = *(const uint4*)&g_khi[src + uu*8];
            }
            #pragma unroll
            for (int uu = 0; uu < 4; uu++) {
                *(uint4*)&Kl[kr*72 + kc0 + uu*8] = *(const uint4*)&g_klo[src + uu*8];
            }
        }
        __syncthreads();

        float c8[8][4] = {};
        #pragma unroll
        for (int ks = 0; ks < 4; ks++) {
            u32 ah0, ah1, ah2, ah3, al0, al1, al2, al3;
            ldsm_x4(ah0, ah1, ah2, ah3, a_base + ks*32);
            ldsm_x4(al0, al1, al2, al3, a_base + QLO_OFF + ks*32);
            #pragma unroll
            for (int j = 0; j < 8; j++) {
                u32 bh0, bh1, bl0, bl1;
                u32 boff = b_base + (u32)j*(8*72*2) + ks*32;
                ldsm_x2(bh0, bh1, boff);
                ldsm_x2(bl0, bl1, boff + KLO_OFF);
                mma_f16(c8[j], ah0, ah1, ah2, ah3, bh0, bh1);
                mma_f16(c8[j], ah0, ah1, ah2, ah3, bl0, bl1);
                mma_f16(c8[j], al0, al1, al2, al3, bh0, bh1);
            }
        }
        #pragma unroll
        for (int j = 0; j < 8; j++) {
            int col = kh0 + 8*j + 2*tig;
            *(float2*)&Ss[(q0w + gid    )*132 + col] = make_float2(c8[j][0], c8[j][1]);
            *(float2*)&Ss[(q0w + gid + 8)*132 + col] = make_float2(c8[j][2], c8[j][3]);
        }
        __syncthreads();

        const float4* srow = (const float4*)&Ss[qrow*132 + seg*32];
        int cb = j0 + seg*32;
        #pragma unroll
        for (int vv = 0; vv < 8; vv++) {
            float4 s4 = srow[vv];
            float m4 = fmaxf(fmaxf(s4.x, s4.y), fmaxf(s4.z, s4.w));
            if (m4 > tmin) {
                tk_push(s4.x, cb + vv*4 + 0, tv, ti, tmin, tpos);
                tk_push(s4.y, cb + vv*4 + 1, tv, ti, tmin, tpos);
                tk_push(s4.z, cb + vv*4 + 2, tv, ti, tmin, tpos);
                tk_push(s4.w, cb + vv*4 + 3, tv, ti, tmin, tpos);
            }
        }
    }
    __syncthreads();

    float* cval = Ss;
    int*   cidx = (int*)(Ss + 2048);
    #pragma unroll
    for (int p = 0; p < 8; p++) { cval[t*8 + p] = tv[p]; cidx[t*8 + p] = ti[p]; }
    __syncthreads();
    if (t < 64) {
        float fv[8]; int fi[8]; float fmin = -INFINITY; int fpos = 0;
        #pragma unroll
        for (int p = 0; p < 8; p++) { fv[p] = -INFINITY; fi[p] = 0; }
        for (int g = 0; g < 4; g++) {
            int src = t + g*64;
            #pragma unroll
            for (int p = 0; p < 8; p++) {
                tk_push(cval[src*8 + p], cidx[src*8 + p], fv, fi, fmin, fpos);
            }
        }
        #pragma unroll
        for (int p = 0; p < 8; p++) {
            g_idx[((size_t)h*BNR + q0 + t)*IPQ + p] = fi[p];
        }
    }
}

// --------------------- gather k_m / v_m from idx -----------------------------
__global__ void gather_kernel(const float* __restrict__ kmem0, const float* __restrict__ vmem0)
{
    int e = blockIdx.x * 256 + threadIdx.x;
    int c  = e & 1023;
    int m2 = (e >> 10) & 4095;
    int b  = e >> 22;
    int h = c >> 6, d = c & 63;
    int nq = m2 >> 3, ip = m2 & 7;
    int f = b * NN + nq;
    int row = g_idx[((size_t)h*BNR + f)*IPQ + ip];
    float kv, vv;
    if (row < MOLD) {
        size_t base = ((size_t)h*MEMS + row + BNR)*HD + d;
        kv = kmem0[base]; vv = vmem0[base];
    } else {
        int fl = row - MOLD;
        size_t base = (size_t)fl*DIN + h*HD + d;
        kv = g_k[base]; vv = g_v[base];
    }
    g_km[e] = kv;
    g_vm[e] = vv;
}

// ------------------- flash attention, 64-q tiles, parallel softmax ----------
// QK ownership: 4q x 4j per thread (qg = t>>4, jg = t&15; 16 lanes per row).
// PV ownership: 1q x 16d per thread (qown = t>>2, ds0 = (t&3)*16).
__global__ void __launch_bounds__(256, 2)
flash_attn(const float* __restrict__ Qbuf, const float* __restrict__ Ksrc,
           const float* __restrict__ Vsrc, float* __restrict__ Obuf, int m)
{
    extern __shared__ float sm[];
    float* Qs_ = sm;                // 64*68  (q-major)
    float* Ks_ = Qs_ + 64*68;       // 64*68  (d-major)
    float* Vs_ = Ks_ + 64*68;       // 64*68  (j-major)
    float* Ss_ = Vs_ + 64*68;       // 64*68
    float* mrow = Ss_ + 64*68;      // 64
    float* lrow = mrow + 64;        // 64
    float* fac  = lrow + 64;        // 64

    int t = threadIdx.x;
    int b = blockIdx.z, h = blockIdx.y;
    int f0 = b * NN + blockIdx.x * 64;

    {
        int r = t >> 2, c0 = (t & 3) * 16;
        size_t src = (size_t)(f0 + r)*DIN + h*HD + c0;
        #pragma unroll
        for (int u = 0; u < 4; u++) {
            *(float4*)&Qs_[r*68 + c0 + u*4] = *(const float4*)&Qbuf[src + u*4];
        }
    }
    if (t < 64) { mrow[t] = -INFINITY; lrow[t] = 0.0f; }

    float o[16] = {};
    int qg = t >> 4, jg = t & 15;
    int qown = t >> 2, ds0 = (t & 3) * 16;
    int jrow = t & 63, jc0 = (t >> 6) * 16;
    __syncthreads();

    for (int j0 = 0; j0 < m; j0 += 64) {
        // load K (transposed to d-major) and V
        {
            size_t src = ((size_t)b*m + j0 + jrow)*DIN + h*HD + jc0;
            #pragma unroll
            for (int u = 0; u < 4; u++) {
                float4 kv = *(const float4*)&Ksrc[src + u*4];
                Ks_[(jc0 + u*4 + 0)*68 + jrow] = kv.x;
                Ks_[(jc0 + u*4 + 1)*68 + jrow] = kv.y;
                Ks_[(jc0 + u*4 + 2)*68 + jrow] = kv.z;
                Ks_[(jc0 + u*4 + 3)*68 + jrow] = kv.w;
            }
            #pragma unroll
            for (int u = 0; u < 4; u++) {
                *(float4*)&Vs_[jrow*68 + jc0 + u*4] = *(const float4*)&Vsrc[src + u*4];
            }
        }
        __syncthreads();

        // QK: 4q x 4j per thread
        float acc[4][4] = {};
        #pragma unroll
        for (int d4 = 0; d4 < 16; d4++) {
            float4 a0 = *(const float4*)&Qs_[(qg*4+0)*68 + d4*4];
            float4 a1 = *(const float4*)&Qs_[(qg*4+1)*68 + d4*4];
            float4 a2 = *(const float4*)&Qs_[(qg*4+2)*68 + d4*4];
            float4 a3 = *(const float4*)&Qs_[(qg*4+3)*68 + d4*4];
            #pragma unroll
            for (int dd = 0; dd < 4; dd++) {
                float4 bv = *(const float4*)&Ks_[(d4*4+dd)*68 + jg*4];
                float x0 = ((const float*)&a0)[dd];
                float x1 = ((const float*)&a1)[dd];
                float x2 = ((const float*)&a2)[dd];
                float x3 = ((const float*)&a3)[dd];
                acc[0][0] += x0*bv.x; acc[0][1] += x0*bv.y; acc[0][2] += x0*bv.z; acc[0][3] += x0*bv.w;
                acc[1][0] += x1*bv.x; acc[1][1] += x1*bv.y; acc[1][2] += x1*bv.z; acc[1][3] += x1*bv.w;
                acc[2][0] += x2*bv.x; acc[2][1] += x2*bv.y; acc[2][2] += x2*bv.z; acc[2][3] += x2*bv.w;
                acc[3][0] += x3*bv.x; acc[3][1] += x3*bv.y; acc[3][2] += x3*bv.z; acc[3][3] += x3*bv.w;
            }
        }

        // parallel online softmax (16 lanes per row, butterfly over jg)
        #pragma unroll
        for (int i = 0; i < 4; i++) {
            int row = qg*4 + i;
            float s0 = acc[i][0]*SCALE, s1 = acc[i][1]*SCALE;
            float s2 = acc[i][2]*SCALE, s3 = acc[i][3]*SCALE;
            float rm = fmaxf(fmaxf(s0, s1), fmaxf(s2, s3));
            #pragma unroll
            for (int wdt = 1; wdt < 16; wdt <<= 1) {
                rm = fmaxf(rm, __shfl_xor_sync(0xffffffffu, rm, wdt, 16));
            }
            float mo = mrow[row];
            float mc = fmaxf(mo, rm);
            float fsc = __expf(mo - mc);
            float e0 = __expf(s0 - mc), e1 = __expf(s1 - mc);
            float e2 = __expf(s2 - mc), e3 = __expf(s3 - mc);
            float rs = e0 + e1 + e2 + e3;
            #pragma unroll
            for (int wdt = 1; wdt < 16; wdt <<= 1) {
                rs += __shfl_xor_sync(0xffffffffu, rs, wdt, 16);
            }
            // all 16 lanes write identical values (warp-synchronous, same path)
            float lold = lrow[row];
            mrow[row] = mc;
            lrow[row] = lold * fsc + rs;
            fac[row]  = fsc;
            *(float4*)&Ss_[row*68 + jg*4] = make_float4(e0, e1, e2, e3);
        }
        __syncthreads();

        // PV: 1q x 16d per thread
        float fq = fac[qown];
        #pragma unroll
        for (int u = 0; u < 16; u++) o[u] *= fq;
        for (int j = 0; j < 64; j++) {
            float p = Ss_[qown*68 + j];
            const float* vr = &Vs_[j*68 + ds0];
            float4 v0 = *(const float4*)&vr[0];
            float4 v1 = *(const float4*)&vr[4];
            float4 v2 = *(const float4*)&vr[8];
            float4 v3 = *(const float4*)&vr[12];
            o[0]  += p*v0.x; o[1]  += p*v0.y; o[2]  += p*v0.z; o[3]  += p*v0.w;
            o[4]  += p*v1.x; o[5]  += p*v1.y; o[6]  += p*v1.z; o[7]  += p*v1.w;
            o[8]  += p*v2.x; o[9]  += p*v2.y; o[10] += p*v2.z; o[11] += p*v2.w;
            o[12] += p*v3.x; o[13] += p*v3.y; o[14] += p*v3.z; o[15] += p*v3.w;
        }
        __syncthreads();
    }
    float inv = 1.0f / lrow[qown];
    size_t dst = (size_t)(f0 + qown)*DOUT + h*HD + ds0;
    #pragma unroll
    for (int u = 0; u < 4; u++) {
        float4 ov = make_float4(o[u*4]*inv, o[u*4+1]*inv, o[u*4+2]*inv, o[u*4+3]*inv);
        *(float4*)&Obuf[dst + u*4] = ov;
    }
}

// ---------------------------- gate combine -----------------------------------
__global__ void combine_kernel(float* __restrict__ out)
{
    int e = blockIdx.x * 256 + threadIdx.x;
    float w = g_w[e];
    out[e] = w * g_c1[e] + (1.0f - w) * g_c2[e];
}

// ------------------------------- launch --------------------------------------
extern "C" void kernel_launch(void* const* d_in, const int* in_sizes, int n_in,
                              void* d_out, int out_size)
{
    const float* x     = (const float*)d_in[0];
    const float* Wq    = (const float*)d_in[1];
    const float* Wk    = (const float*)d_in[2];
    const float* Wv    = (const float*)d_in[3];
    const float* Ww    = (const float*)d_in[4];
    const float* Wo    = (const float*)d_in[5];
    const float* bo    = (const float*)d_in[6];
    const float* kmem0 = (const float*)d_in[7];
    const float* vmem0 = (const float*)d_in[8];
    float* out = (float*)d_out;

    float *q, *k, *v, *w, *ao, *aom, *c1, *c2, *km, *vm;
    cudaGetSymbolAddress((void**)&q,   g_q);
    cudaGetSymbolAddress((void**)&k,   g_k);
    cudaGetSymbolAddress((void**)&v,   g_v);
    cudaGetSymbolAddress((void**)&w,   g_w);
    cudaGetSymbolAddress((void**)&ao,  g_ao);
    cudaGetSymbolAddress((void**)&aom, g_aom);
    cudaGetSymbolAddress((void**)&c1,  g_c1);
    cudaGetSymbolAddress((void**)&c2,  g_c2);
    cudaGetSymbolAddress((void**)&km,  g_km);
    cudaGetSymbolAddress((void**)&vm,  g_vm);

    const int SIMS_SMEM  = (2*64*72 + 2*128*72)*2 + 64*132*4;   // 89088
    const int FLASH_SMEM = (4*64*68 + 3*64)*4;                  // 70400
    cudaFuncSetAttribute(sims_topk,  cudaFuncAttributeMaxDynamicSharedMemorySize, SIMS_SMEM);
    cudaFuncSetAttribute(flash_attn, cudaFuncAttributeMaxDynamicSharedMemorySize, FLASH_SMEM);

    dim3 gemm_grid(DOUT/128, BNR/128);

    sgemm_abt<<<gemm_grid, 256>>>(x, Wq, q, BNR, DIN,  DIN, 0, 0);
    sgemm_abt<<<gemm_grid, 256>>>(x, Wk, k, BNR, DIN,  DIN, 0, 0);
    sgemm_abt<<<gemm_grid, 256>>>(x, Wv, v, BNR, DOUT, DIN, 0, 0);
    sgemm_abt<<<gemm_grid, 256>>>(x, Ww, w, BNR, DOUT, DIN, 0, 1);

    convert_q<<<(H*BNR*HD)/256, 256>>>();
    convert_k<<<(H*MEMS*HD)/256, 256>>>(kmem0);

    flash_attn<<<dim3(NN/64, H, BB), 256, FLASH_SMEM>>>(q, k, v, ao, NN);

    sims_topk<<<dim3(BNR/64, H), 256, SIMS_SMEM>>>();

    gather_kernel<<<(BB*NN*IPQ*DIN)/256, 256>>>(kmem0, vmem0);

    flash_attn<<<dim3(NN/64, H, BB), 256, FLASH_SMEM>>>(q, km, vm, aom, NN*IPQ);

    sgemm_abt<<<gemm_grid, 256>>>(ao,  Wo, c1, BNR, DOUT, DOUT, bo, 0);
    sgemm_abt<<<gemm_grid, 256>>>(aom, Wo, c2, BNR, DOUT, DOUT, bo, 0);

    combine_kernel<<<(BNR*DOUT)/256, 256>>>(out);
}

// round 10
// speedup vs baseline: 1.8281x; 1.0967x over previous
#include <cuda_runtime.h>
#include <cuda_fp16.h>
#include <cstdint>
#include <cstdio>
#include <math.h>

typedef unsigned int u32;

#define H    16
#define HD   64
#define MEMS 32768
#define IPQ  8
#define NCAND 16
#define BB   4
#define NN   512
#define DIN  1024
#define DOUT 1024
#define BNR  (BB*NN)
#define MOLD (MEMS - BNR)
#define SCALE 0.125f

// ------------------------- scratch (device globals) -------------------------
__device__ float g_q  [BNR*DIN];
__device__ float g_k  [BNR*DIN];
__device__ float g_v  [BNR*DOUT];
__device__ float g_w  [BNR*DOUT];
__device__ float g_ao [BNR*DOUT];
__device__ float g_aom[BNR*DOUT];
__device__ float g_c1 [BNR*DOUT];
__device__ float g_c2 [BNR*DOUT];
__device__ float g_km [(size_t)BB*(NN*IPQ)*DIN];
__device__ float g_vm [(size_t)BB*(NN*IPQ)*DOUT];
__device__ int   g_idx [H*BNR*IPQ];
__device__ int   g_cand[(size_t)H*BNR*NCAND];
// fp16 hi planes, head-major
__device__ __half g_qhi[(size_t)H*BNR*HD];
__device__ __half g_khi[(size_t)H*MEMS*HD];

// ------------------------- helpers -------------------------
__device__ __forceinline__ u32 smem_u32(const void* p) {
    return (u32)__cvta_generic_to_shared(p);
}
__device__ __forceinline__ void ldsm_x4(u32 &r0, u32 &r1, u32 &r2, u32 &r3, u32 addr) {
    asm volatile("ldmatrix.sync.aligned.m8n8.x4.shared.b16 {%0,%1,%2,%3}, [%4];"
        : "=r"(r0), "=r"(r1), "=r"(r2), "=r"(r3) : "r"(addr));
}
__device__ __forceinline__ void ldsm_x2(u32 &r0, u32 &r1, u32 addr) {
    asm volatile("ldmatrix.sync.aligned.m8n8.x2.shared.b16 {%0,%1}, [%2];"
        : "=r"(r0), "=r"(r1) : "r"(addr));
}
__device__ __forceinline__ void mma_f16(float* c, u32 a0, u32 a1, u32 a2, u32 a3,
                                        u32 b0, u32 b1) {
    asm volatile("mma.sync.aligned.m16n8k16.row.col.f32.f16.f16.f32 "
        "{%0,%1,%2,%3}, {%4,%5,%6,%7}, {%8,%9}, {%0,%1,%2,%3};"
        : "+f"(c[0]), "+f"(c[1]), "+f"(c[2]), "+f"(c[3])
        : "r"(a0), "r"(a1), "r"(a2), "r"(a3), "r"(b0), "r"(b1));
}

// ------------------------- SGEMM: C = A * B^T ------------------------
__global__ void __launch_bounds__(256, 2)
sgemm_abt(const float* __restrict__ A, const float* __restrict__ B,
          float* __restrict__ C, int M, int N, int K,
          const float* __restrict__ bias, int do_sigmoid)
{
    __shared__ float As[16][132];
    __shared__ float Bs[16][132];
    int t  = threadIdx.x;
    int tx = t & 15, ty = t >> 4;
    int row0 = blockIdx.y * 128, col0 = blockIdx.x * 128;
    float acc[8][8] = {};

    for (int k0 = 0; k0 < K; k0 += 16) {
        #pragma unroll
        for (int vv = 0; vv < 2; vv++) {
            int lin = t + vv * 256;
            int r   = lin >> 2;
            int kq  = (lin & 3) * 4;
            float4 av = *(const float4*)&A[(size_t)(row0 + r) * K + k0 + kq];
            As[kq+0][r] = av.x; As[kq+1][r] = av.y; As[kq+2][r] = av.z; As[kq+3][r] = av.w;
            float4 bv = *(const float4*)&B[(size_t)(col0 + r) * K + k0 + kq];
            Bs[kq+0][r] = bv.x; Bs[kq+1][r] = bv.y; Bs[kq+2][r] = bv.z; Bs[kq+3][r] = bv.w;
        }
        __syncthreads();
        #pragma unroll
        for (int kk = 0; kk < 16; kk++) {
            float a[8], b[8];
            *(float4*)&a[0] = *(const float4*)&As[kk][ty*8];
            *(float4*)&a[4] = *(const float4*)&As[kk][ty*8 + 4];
            *(float4*)&b[0] = *(const float4*)&Bs[kk][tx*8];
            *(float4*)&b[4] = *(const float4*)&Bs[kk][tx*8 + 4];
            #pragma unroll
            for (int i = 0; i < 8; i++) {
                #pragma unroll
                for (int j = 0; j < 8; j++) {
                    acc[i][j] += a[i] * b[j];
                }
            }
        }
        __syncthreads();
    }
    #pragma unroll
    for (int i = 0; i < 8; i++) {
        int r = row0 + ty*8 + i;
        #pragma unroll
        for (int j = 0; j < 8; j++) {
            int c = col0 + tx*8 + j;
            float v = acc[i][j];
            if (bias) v += bias[c];
            if (do_sigmoid) v = 1.0f / (1.0f + __expf(-v));
            C[(size_t)r * N + c] = v;
        }
    }
}

// ------------------- fp16 hi-plane precompute ----------------------------
__global__ void convert_k(const float* __restrict__ kmem0)
{
    int e = blockIdx.x * 256 + threadIdx.x;
    int d = e & 63;
    int j = (e >> 6) & (MEMS - 1);
    int h = e >> 21;
    float val = (j < MOLD)
        ? kmem0[((size_t)h*MEMS + j + BNR)*HD + d]
        : g_k[(size_t)(j - MOLD)*DIN + h*HD + d];
    g_khi[e] = __float2half_rn(val);
}

__global__ void convert_q()
{
    int e = blockIdx.x * 256 + threadIdx.x;
    int d = e & 63;
    int r = (e >> 6) & (BNR - 1);
    int h = e >> 17;
    g_qhi[e] = __float2half_rn(g_q[(size_t)r*DIN + h*HD + d]);
}

// ------------------------- top-K push helpers -------------------------
__device__ __forceinline__ void tk_push8(float s, int id, float* tv, int* ti,
                                         float &tmin, int &tpos) {
    if (s > tmin) {
        tv[tpos] = s; ti[tpos] = id;
        tmin = tv[0]; tpos = 0;
        #pragma unroll
        for (int p = 1; p < 8; p++) {
            if (tv[p] < tmin) { tmin = tv[p]; tpos = p; }
        }
    }
}
__device__ __forceinline__ void tk_push16(float s, int id, float* tv, int* ti,
                                          float &tmin, int &tpos) {
    if (s > tmin) {
        tv[tpos] = s; ti[tpos] = id;
        tmin = tv[0]; tpos = 0;
        #pragma unroll
        for (int p = 1; p < 16; p++) {
            if (tv[p] < tmin) { tmin = tv[p]; tpos = p; }
        }
    }
}

// --------------- coarse sims + top-16 candidates via fp16 HMMA -------------
// grid (32, 16): blockIdx.x = 64-query tile, blockIdx.y = head. 256 thr, 8 warps.
__global__ void __launch_bounds__(256, 2)
sims_topk()
{
    extern __shared__ char smraw[];
    __half* Qh = (__half*)smraw;                  // [64][72]
    __half* Kh = Qh + 64*72;                      // [128][72]
    float* Ss = (float*)(smraw + (64*72 + 128*72)*2);   // [64][132]

    int t = threadIdx.x;
    int h = blockIdx.y;
    int q0 = blockIdx.x * 64;
    int lane = t & 31, warp = t >> 5;
    int gid = lane >> 2, tig = lane & 3;

    // load Q hi plane (vectorized)
    {
        int r = t >> 2, c0 = (t & 3) * 16;
        size_t src = ((size_t)h*BNR + q0 + r)*HD + c0;
        *(uint4*)&Qh[r*72 + c0    ] = *(const uint4*)&g_qhi[src];
        *(uint4*)&Qh[r*72 + c0 + 8] = *(const uint4*)&g_qhi[src + 8];
    }

    float tv[8]; int ti[8];
    #pragma unroll
    for (int p = 0; p < 8; p++) { tv[p] = -INFINITY; ti[p] = 0; }
    float tmin = -INFINITY; int tpos = 0;

    int q0w = (warp >> 1) * 16;
    int kh0 = (warp & 1) * 64;

    u32 a_base = smem_u32(&Qh[(q0w + (lane & 15))*72 + ((lane >> 4) & 1)*8]);
    u32 b_base = smem_u32(&Kh[(kh0 + (lane & 7))*72 + ((lane >> 3) & 1)*8]);

    int qrow = t & 63, seg = t >> 6;
    int kr = t >> 1, kc0 = (t & 1) * 32;

    for (int tile = 0; tile < MEMS/128; tile++) {
        int j0 = tile * 128;
        {
            size_t src = ((size_t)h*MEMS + j0 + kr)*HD + kc0;
            #pragma unroll
            for (int uu = 0; uu < 4; uu++) {
                *(uint4*)&Kh[kr*72 + kc0 + uu*8] = *(const uint4*)&g_khi[src + uu*8];
            }
        }
        __syncthreads();

        float c8[8][4] = {};
        #pragma unroll
        for (int ks = 0; ks < 4; ks++) {
            u32 a0, a1, a2, a3;
            ldsm_x4(a0, a1, a2, a3, a_base + ks*32);
            #pragma unroll
            for (int j = 0; j < 8; j++) {
                u32 b0, b1;
                ldsm_x2(b0, b1, b_base + (u32)j*(8*72*2) + ks*32);
                mma_f16(c8[j], a0, a1, a2, a3, b0, b1);
            }
        }
        #pragma unroll
        for (int j = 0; j < 8; j++) {
            int col = kh0 + 8*j + 2*tig;
            *(float2*)&Ss[(q0w + gid    )*132 + col] = make_float2(c8[j][0], c8[j][1]);
            *(float2*)&Ss[(q0w + gid + 8)*132 + col] = make_float2(c8[j][2], c8[j][3]);
        }
        __syncthreads();

        const float4* srow = (const float4*)&Ss[qrow*132 + seg*32];
        int cb = j0 + seg*32;
        #pragma unroll
        for (int vv = 0; vv < 8; vv++) {
            float4 s4 = srow[vv];
            float m4 = fmaxf(fmaxf(s4.x, s4.y), fmaxf(s4.z, s4.w));
            if (m4 > tmin) {
                tk_push8(s4.x, cb + vv*4 + 0, tv, ti, tmin, tpos);
                tk_push8(s4.y, cb + vv*4 + 1, tv, ti, tmin, tpos);
                tk_push8(s4.z, cb + vv*4 + 2, tv, ti, tmin, tpos);
                tk_push8(s4.w, cb + vv*4 + 3, tv, ti, tmin, tpos);
            }
        }
    }
    __syncthreads();

    // merge 4 partial top-8 lists -> top-16 candidates per query
    float* cval = Ss;
    int*   cidx = (int*)(Ss + 2048);
    #pragma unroll
    for (int p = 0; p < 8; p++) { cval[t*8 + p] = tv[p]; cidx[t*8 + p] = ti[p]; }
    __syncthreads();
    if (t < 64) {
        float fv[16]; int fi[16]; float fmin = -INFINITY; int fpos = 0;
        #pragma unroll
        for (int p = 0; p < 16; p++) { fv[p] = -INFINITY; fi[p] = 0; }
        for (int g = 0; g < 4; g++) {
            int src = t + g*64;
            #pragma unroll
            for (int p = 0; p < 8; p++) {
                tk_push16(cval[src*8 + p], cidx[src*8 + p], fv, fi, fmin, fpos);
            }
        }
        #pragma unroll
        for (int p = 0; p < 16; p++) {
            g_cand[((size_t)h*BNR + q0 + t)*NCAND + p] = fi[p];
        }
    }
}

// --------------- exact fp32 rescore of 16 candidates -> top-8 ---------------
// one warp per (h, query); lanes 0-15 own one candidate each.
__global__ void __launch_bounds__(256)
rescore_kernel(const float* __restrict__ kmem0)
{
    int e = blockIdx.x * 8 + (threadIdx.x >> 5);   // 0 .. H*BNR-1
    int lane = threadIdx.x & 31;
    int h = e >> 11, f = e & (BNR - 1);

    float s = -INFINITY;
    int myidx = -1;
    if (lane < NCAND) {
        myidx = g_cand[(size_t)e*NCAND + lane];
        const float* qrow = &g_q[(size_t)f*DIN + h*HD];
        const float* krow = (myidx < MOLD)
            ? &kmem0[((size_t)h*MEMS + myidx + BNR)*HD]
            : &g_k[(size_t)(myidx - MOLD)*DIN + h*HD];
        float acc = 0.0f;
        #pragma unroll
        for (int d4 = 0; d4 < 16; d4++) {
            float4 qv = *(const float4*)&qrow[d4*4];
            float4 kv = *(const float4*)&krow[d4*4];
            acc += qv.x*kv.x + qv.y*kv.y + qv.z*kv.z + qv.w*kv.w;
        }
        s = acc;
    }
    #pragma unroll
    for (int p = 0; p < IPQ; p++) {
        float m = s;
        #pragma unroll
        for (int o = 16; o >= 1; o >>= 1) {
            m = fmaxf(m, __shfl_xor_sync(0xffffffffu, m, o));
        }
        unsigned msk = __ballot_sync(0xffffffffu, s == m);
        int src = __ffs(msk) - 1;
        if (lane == src) {
            g_idx[(size_t)e*IPQ + p] = myidx;
            s = -INFINITY;
        }
    }
}

// --------------------- gather k_m / v_m from idx -----------------------------
__global__ void gather_kernel(const float* __restrict__ kmem0, const float* __restrict__ vmem0)
{
    int e = blockIdx.x * 256 + threadIdx.x;
    int c  = e & 1023;
    int m2 = (e >> 10) & 4095;
    int b  = e >> 22;
    int h = c >> 6, d = c & 63;
    int nq = m2 >> 3, ip = m2 & 7;
    int f = b * NN + nq;
    int row = g_idx[((size_t)h*BNR + f)*IPQ + ip];
    float kv, vv;
    if (row < MOLD) {
        size_t base = ((size_t)h*MEMS + row + BNR)*HD + d;
        kv = kmem0[base]; vv = vmem0[base];
    } else {
        int fl = row - MOLD;
        size_t base = (size_t)fl*DIN + h*HD + d;
        kv = g_k[base]; vv = g_v[base];
    }
    g_km[e] = kv;
    g_vm[e] = vv;
}

// ------------------- flash attention, 64-q tiles, parallel softmax ----------
__global__ void __launch_bounds__(256, 2)
flash_attn(const float* __restrict__ Qbuf, const float* __restrict__ Ksrc,
           const float* __restrict__ Vsrc, float* __restrict__ Obuf, int m)
{
    extern __shared__ float sm[];
    float* Qs_ = sm;                // 64*68
    float* Ks_ = Qs_ + 64*68;       // 64*68  (d-major)
    float* Vs_ = Ks_ + 64*68;       // 64*68
    float* Ss_ = Vs_ + 64*68;       // 64*68
    float* mrow = Ss_ + 64*68;
    float* lrow = mrow + 64;
    float* fac  = lrow + 64;

    int t = threadIdx.x;
    int b = blockIdx.z, h = blockIdx.y;
    int f0 = b * NN + blockIdx.x * 64;

    {
        int r = t >> 2, c0 = (t & 3) * 16;
        size_t src = (size_t)(f0 + r)*DIN + h*HD + c0;
        #pragma unroll
        for (int u = 0; u < 4; u++) {
            *(float4*)&Qs_[r*68 + c0 + u*4] = *(const float4*)&Qbuf[src + u*4];
        }
    }
    if (t < 64) { mrow[t] = -INFINITY; lrow[t] = 0.0f; }

    float o[16] = {};
    int qg = t >> 4, jg = t & 15;
    int qown = t >> 2, ds0 = (t & 3) * 16;
    int jrow = t & 63, jc0 = (t >> 6) * 16;
    __syncthreads();

    for (int j0 = 0; j0 < m; j0 += 64) {
        {
            size_t src = ((size_t)b*m + j0 + jrow)*DIN + h*HD + jc0;
            #pragma unroll
            for (int u = 0; u < 4; u++) {
                float4 kv = *(const float4*)&Ksrc[src + u*4];
                Ks_[(jc0 + u*4 + 0)*68 + jrow] = kv.x;
                Ks_[(jc0 + u*4 + 1)*68 + jrow] = kv.y;
                Ks_[(jc0 + u*4 + 2)*68 + jrow] = kv.z;
                Ks_[(jc0 + u*4 + 3)*68 + jrow] = kv.w;
            }
            #pragma unroll
            for (int u = 0; u < 4; u++) {
                *(float4*)&Vs_[jrow*68 + jc0 + u*4] = *(const float4*)&Vsrc[src + u*4];
            }
        }
        __syncthreads();

        float acc[4][4] = {};
        #pragma unroll
        for (int d4 = 0; d4 < 16; d4++) {
            float4 a0 = *(const float4*)&Qs_[(qg*4+0)*68 + d4*4];
            float4 a1 = *(const float4*)&Qs_[(qg*4+1)*68 + d4*4];
            float4 a2 = *(const float4*)&Qs_[(qg*4+2)*68 + d4*4];
            float4 a3 = *(const float4*)&Qs_[(qg*4+3)*68 + d4*4];
            #pragma unroll
            for (int dd = 0; dd < 4; dd++) {
                float4 bv = *(const float4*)&Ks_[(d4*4+dd)*68 + jg*4];
                float x0 = ((const float*)&a0)[dd];
                float x1 = ((const float*)&a1)[dd];
                float x2 = ((const float*)&a2)[dd];
                float x3 = ((const float*)&a3)[dd];
                acc[0][0] += x0*bv.x; acc[0][1] += x0*bv.y; acc[0][2] += x0*bv.z; acc[0][3] += x0*bv.w;
                acc[1][0] += x1*bv.x; acc[1][1] += x1*bv.y; acc[1][2] += x1*bv.z; acc[1][3] += x1*bv.w;
                acc[2][0] += x2*bv.x; acc[2][1] += x2*bv.y; acc[2][2] += x2*bv.z; acc[2][3] += x2*bv.w;
                acc[3][0] += x3*bv.x; acc[3][1] += x3*bv.y; acc[3][2] += x3*bv.z; acc[3][3] += x3*bv.w;
            }
        }

        #pragma unroll
        for (int i = 0; i < 4; i++) {
            int row = qg*4 + i;
            float s0 = acc[i][0]*SCALE, s1 = acc[i][1]*SCALE;
            float s2 = acc[i][2]*SCALE, s3 = acc[i][3]*SCALE;
            float rm = fmaxf(fmaxf(s0, s1), fmaxf(s2, s3));
            #pragma unroll
            for (int wdt = 1; wdt < 16; wdt <<= 1) {
                rm = fmaxf(rm, __shfl_xor_sync(0xffffffffu, rm, wdt, 16));
            }
            float mo = mrow[row];
            float mc = fmaxf(mo, rm);
            float fsc = __expf(mo - mc);
            float e0 = __expf(s0 - mc), e1 = __expf(s1 - mc);
            float e2 = __expf(s2 - mc), e3 = __expf(s3 - mc);
            float rs = e0 + e1 + e2 + e3;
            #pragma unroll
            for (int wdt = 1; wdt < 16; wdt <<= 1) {
                rs += __shfl_xor_sync(0xffffffffu, rs, wdt, 16);
            }
            float lold = lrow[row];
            mrow[row] = mc;
            lrow[row] = lold * fsc + rs;
            fac[row]  = fsc;
            *(float4*)&Ss_[row*68 + jg*4] = make_float4(e0, e1, e2, e3);
        }
        __syncthreads();

        float fq = fac[qown];
        #pragma unroll
        for (int u = 0; u < 16; u++) o[u] *= fq;
        for (int j = 0; j < 64; j++) {
            float p = Ss_[qown*68 + j];
            const float* vr = &Vs_[j*68 + ds0];
            float4 v0 = *(const float4*)&vr[0];
            float4 v1 = *(const float4*)&vr[4];
            float4 v2 = *(const float4*)&vr[8];
            float4 v3 = *(const float4*)&vr[12];
            o[0]  += p*v0.x; o[1]  += p*v0.y; o[2]  += p*v0.z; o[3]  += p*v0.w;
            o[4]  += p*v1.x; o[5]  += p*v1.y; o[6]  += p*v1.z; o[7]  += p*v1.w;
            o[8]  += p*v2.x; o[9]  += p*v2.y; o[10] += p*v2.z; o[11] += p*v2.w;
            o[12] += p*v3.x; o[13] += p*v3.y; o[14] += p*v3.z; o[15] += p*v3.w;
        }
        __syncthreads();
    }
    float inv = 1.0f / lrow[qown];
    size_t dst = (size_t)(f0 + qown)*DOUT + h*HD + ds0;
    #pragma unroll
    for (int u = 0; u < 4; u++) {
        float4 ov = make_float4(o[u*4]*inv, o[u*4+1]*inv, o[u*4+2]*inv, o[u*4+3]*inv);
        *(float4*)&Obuf[dst + u*4] = ov;
    }
}

// ---------------------------- gate combine -----------------------------------
__global__ void combine_kernel(float* __restrict__ out)
{
    int e = blockIdx.x * 256 + threadIdx.x;
    float w = g_w[e];
    out[e] = w * g_c1[e] + (1.0f - w) * g_c2[e];
}

// ------------------------------- launch --------------------------------------
extern "C" void kernel_launch(void* const* d_in, const int* in_sizes, int n_in,
                              void* d_out, int out_size)
{
    const float* x     = (const float*)d_in[0];
    const float* Wq    = (const float*)d_in[1];
    const float* Wk    = (const float*)d_in[2];
    const float* Wv    = (const float*)d_in[3];
    const float* Ww    = (const float*)d_in[4];
    const float* Wo    = (const float*)d_in[5];
    const float* bo    = (const float*)d_in[6];
    const float* kmem0 = (const float*)d_in[7];
    const float* vmem0 = (const float*)d_in[8];
    float* out = (float*)d_out;

    float *q, *k, *v, *w, *ao, *aom, *c1, *c2, *km, *vm;
    cudaGetSymbolAddress((void**)&q,   g_q);
    cudaGetSymbolAddress((void**)&k,   g_k);
    cudaGetSymbolAddress((void**)&v,   g_v);
    cudaGetSymbolAddress((void**)&w,   g_w);
    cudaGetSymbolAddress((void**)&ao,  g_ao);
    cudaGetSymbolAddress((void**)&aom, g_aom);
    cudaGetSymbolAddress((void**)&c1,  g_c1);
    cudaGetSymbolAddress((void**)&c2,  g_c2);
    cudaGetSymbolAddress((void**)&km,  g_km);
    cudaGetSymbolAddress((void**)&vm,  g_vm);

    const int SIMS_SMEM  = (64*72 + 128*72)*2 + 64*132*4;   // 61440
    const int FLASH_SMEM = (4*64*68 + 3*64)*4;              // 70400
    cudaFuncSetAttribute(sims_topk,  cudaFuncAttributeMaxDynamicSharedMemorySize, SIMS_SMEM);
    cudaFuncSetAttribute(flash_attn, cudaFuncAttributeMaxDynamicSharedMemorySize, FLASH_SMEM);

    dim3 gemm_grid(DOUT/128, BNR/128);

    sgemm_abt<<<gemm_grid, 256>>>(x, Wq, q, BNR, DIN,  DIN, 0, 0);
    sgemm_abt<<<gemm_grid, 256>>>(x, Wk, k, BNR, DIN,  DIN, 0, 0);
    sgemm_abt<<<gemm_grid, 256>>>(x, Wv, v, BNR, DOUT, DIN, 0, 0);
    sgemm_abt<<<gemm_grid, 256>>>(x, Ww, w, BNR, DOUT, DIN, 0, 1);

    convert_q<<<(H*BNR*HD)/256, 256>>>();
    convert_k<<<(H*MEMS*HD)/256, 256>>>(kmem0);

    flash_attn<<<dim3(NN/64, H, BB), 256, FLASH_SMEM>>>(q, k, v, ao, NN);

    // coarse candidates (fp16 HMMA) then exact fp32 rescore -> top-8
    sims_topk<<<dim3(BNR/64, H), 256, SIMS_SMEM>>>();
    rescore_kernel<<<(H*BNR)/8, 256>>>(kmem0);

    gather_kernel<<<(BB*NN*IPQ*DIN)/256, 256>>>(kmem0, vmem0);

    flash_attn<<<dim3(NN/64, H, BB), 256, FLASH_SMEM>>>(q, km, vm, aom, NN*IPQ);

    sgemm_abt<<<gemm_grid, 256>>>(ao,  Wo, c1, BNR, DOUT, DOUT, bo, 0);
    sgemm_abt<<<gemm_grid, 256>>>(aom, Wo, c2, BNR, DOUT, DOUT, bo, 0);

    combine_kernel<<<(BNR*DOUT)/256, 256>>>(out);
}

// round 11
// speedup vs baseline: 2.7728x; 1.5168x over previous
#include <cuda_runtime.h>
#include <cuda_fp16.h>
#include <cstdint>
#include <cstdio>
#include <math.h>

typedef unsigned int u32;

#define H    16
#define HD   64
#define MEMS 32768
#define IPQ  8
#define NCAND 16
#define BB   4
#define NN   512
#define DIN  1024
#define DOUT 1024
#define BNR  (BB*NN)
#define MOLD (MEMS - BNR)
#define SCALE 0.125f

// ------------------------- scratch (device globals) -------------------------
__device__ float g_q  [BNR*DIN];
__device__ float g_k  [BNR*DIN];
__device__ float g_v  [BNR*DOUT];
__device__ float g_w  [BNR*DOUT];
__device__ float g_ao [BNR*DOUT];
__device__ float g_aom[BNR*DOUT];
__device__ float g_c1 [BNR*DOUT];
__device__ float g_c2 [BNR*DOUT];
__device__ float g_km [(size_t)BB*(NN*IPQ)*DIN];
__device__ float g_vm [(size_t)BB*(NN*IPQ)*DOUT];
__device__ int   g_idx [H*BNR*IPQ];
__device__ int   g_cand[(size_t)H*BNR*NCAND];
__device__ __half g_qhi[(size_t)H*BNR*HD];
__device__ __half g_khi[(size_t)H*MEMS*HD];

// ------------------------- helpers -------------------------
__device__ __forceinline__ u32 smem_u32(const void* p) {
    return (u32)__cvta_generic_to_shared(p);
}
__device__ __forceinline__ void ldsm_x4(u32 &r0, u32 &r1, u32 &r2, u32 &r3, u32 addr) {
    asm volatile("ldmatrix.sync.aligned.m8n8.x4.shared.b16 {%0,%1,%2,%3}, [%4];"
        : "=r"(r0), "=r"(r1), "=r"(r2), "=r"(r3) : "r"(addr));
}
__device__ __forceinline__ void ldsm_x2(u32 &r0, u32 &r1, u32 addr) {
    asm volatile("ldmatrix.sync.aligned.m8n8.x2.shared.b16 {%0,%1}, [%2];"
        : "=r"(r0), "=r"(r1) : "r"(addr));
}
__device__ __forceinline__ void mma_f16(float* c, u32 a0, u32 a1, u32 a2, u32 a3,
                                        u32 b0, u32 b1) {
    asm volatile("mma.sync.aligned.m16n8k16.row.col.f32.f16.f16.f32 "
        "{%0,%1,%2,%3}, {%4,%5,%6,%7}, {%8,%9}, {%0,%1,%2,%3};"
        : "+f"(c[0]), "+f"(c[1]), "+f"(c[2]), "+f"(c[3])
        : "r"(a0), "r"(a1), "r"(a2), "r"(a3), "r"(b0), "r"(b1));
}

// ------------------------- SGEMM: C = A * B^T ------------------------
__global__ void __launch_bounds__(256, 2)
sgemm_abt(const float* __restrict__ A, const float* __restrict__ B,
          float* __restrict__ C, int M, int N, int K,
          const float* __restrict__ bias, int do_sigmoid)
{
    __shared__ float As[16][132];
    __shared__ float Bs[16][132];
    int t  = threadIdx.x;
    int tx = t & 15, ty = t >> 4;
    int row0 = blockIdx.y * 128, col0 = blockIdx.x * 128;
    float acc[8][8] = {};

    for (int k0 = 0; k0 < K; k0 += 16) {
        #pragma unroll
        for (int vv = 0; vv < 2; vv++) {
            int lin = t + vv * 256;
            int r   = lin >> 2;
            int kq  = (lin & 3) * 4;
            float4 av = *(const float4*)&A[(size_t)(row0 + r) * K + k0 + kq];
            As[kq+0][r] = av.x; As[kq+1][r] = av.y; As[kq+2][r] = av.z; As[kq+3][r] = av.w;
            float4 bv = *(const float4*)&B[(size_t)(col0 + r) * K + k0 + kq];
            Bs[kq+0][r] = bv.x; Bs[kq+1][r] = bv.y; Bs[kq+2][r] = bv.z; Bs[kq+3][r] = bv.w;
        }
        __syncthreads();
        #pragma unroll
        for (int kk = 0; kk < 16; kk++) {
            float a[8], b[8];
            *(float4*)&a[0] = *(const float4*)&As[kk][ty*8];
            *(float4*)&a[4] = *(const float4*)&As[kk][ty*8 + 4];
            *(float4*)&b[0] = *(const float4*)&Bs[kk][tx*8];
            *(float4*)&b[4] = *(const float4*)&Bs[kk][tx*8 + 4];
            #pragma unroll
            for (int i = 0; i < 8; i++) {
                #pragma unroll
                for (int j = 0; j < 8; j++) {
                    acc[i][j] += a[i] * b[j];
                }
            }
        }
        __syncthreads();
    }
    #pragma unroll
    for (int i = 0; i < 8; i++) {
        int r = row0 + ty*8 + i;
        #pragma unroll
        for (int j = 0; j < 8; j++) {
            int c = col0 + tx*8 + j;
            float v = acc[i][j];
            if (bias) v += bias[c];
            if (do_sigmoid) v = 1.0f / (1.0f + __expf(-v));
            C[(size_t)r * N + c] = v;
        }
    }
}

// ------------------- fp16 hi-plane precompute ----------------------------
__global__ void convert_k(const float* __restrict__ kmem0)
{
    int e = blockIdx.x * 256 + threadIdx.x;
    int d = e & 63;
    int j = (e >> 6) & (MEMS - 1);
    int h = e >> 21;
    float val = (j < MOLD)
        ? kmem0[((size_t)h*MEMS + j + BNR)*HD + d]
        : g_k[(size_t)(j - MOLD)*DIN + h*HD + d];
    g_khi[e] = __float2half_rn(val);
}

__global__ void convert_q()
{
    int e = blockIdx.x * 256 + threadIdx.x;
    int d = e & 63;
    int r = (e >> 6) & (BNR - 1);
    int h = e >> 17;
    g_qhi[e] = __float2half_rn(g_q[(size_t)r*DIN + h*HD + d]);
}

// ------------------------- top-K push helpers -------------------------
__device__ __forceinline__ void tk_push8(float s, int id, float* tv, int* ti,
                                         float &tmin, int &tpos) {
    if (s > tmin) {
        tv[tpos] = s; ti[tpos] = id;
        tmin = tv[0]; tpos = 0;
        #pragma unroll
        for (int p = 1; p < 8; p++) {
            if (tv[p] < tmin) { tmin = tv[p]; tpos = p; }
        }
    }
}
__device__ __forceinline__ void tk_push16(float s, int id, float* tv, int* ti,
                                          float &tmin, int &tpos) {
    if (s > tmin) {
        tv[tpos] = s; ti[tpos] = id;
        tmin = tv[0]; tpos = 0;
        #pragma unroll
        for (int p = 1; p < 16; p++) {
            if (tv[p] < tmin) { tmin = tv[p]; tpos = p; }
        }
    }
}

// --------------- coarse sims + top-16 candidates via fp16 HMMA -------------
__global__ void __launch_bounds__(256, 2)
sims_topk()
{
    extern __shared__ char smraw[];
    __half* Qh = (__half*)smraw;                  // [64][72]
    __half* Kh = Qh + 64*72;                      // [128][72]
    float* Ss = (float*)(smraw + (64*72 + 128*72)*2);   // [64][132]

    int t = threadIdx.x;
    int h = blockIdx.y;
    int q0 = blockIdx.x * 64;
    int lane = t & 31, warp = t >> 5;
    int gid = lane >> 2, tig = lane & 3;

    {
        int r = t >> 2, c0 = (t & 3) * 16;
        size_t src = ((size_t)h*BNR + q0 + r)*HD + c0;
        *(uint4*)&Qh[r*72 + c0    ] = *(const uint4*)&g_qhi[src];
        *(uint4*)&Qh[r*72 + c0 + 8] = *(const uint4*)&g_qhi[src + 8];
    }

    float tv[8]; int ti[8];
    #pragma unroll
    for (int p = 0; p < 8; p++) { tv[p] = -INFINITY; ti[p] = 0; }
    float tmin = -INFINITY; int tpos = 0;

    int q0w = (warp >> 1) * 16;
    int kh0 = (warp & 1) * 64;

    u32 a_base = smem_u32(&Qh[(q0w + (lane & 15))*72 + ((lane >> 4) & 1)*8]);
    u32 b_base = smem_u32(&Kh[(kh0 + (lane & 7))*72 + ((lane >> 3) & 1)*8]);

    int qrow = t & 63, seg = t >> 6;
    int kr = t >> 1, kc0 = (t & 1) * 32;

    for (int tile = 0; tile < MEMS/128; tile++) {
        int j0 = tile * 128;
        {
            size_t src = ((size_t)h*MEMS + j0 + kr)*HD + kc0;
            #pragma unroll
            for (int uu = 0; uu < 4; uu++) {
                *(uint4*)&Kh[kr*72 + kc0 + uu*8] = *(const uint4*)&g_khi[src + uu*8];
            }
        }
        __syncthreads();

        float c8[8][4] = {};
        #pragma unroll
        for (int ks = 0; ks < 4; ks++) {
            u32 a0, a1, a2, a3;
            ldsm_x4(a0, a1, a2, a3, a_base + ks*32);
            #pragma unroll
            for (int j = 0; j < 8; j++) {
                u32 b0, b1;
                ldsm_x2(b0, b1, b_base + (u32)j*(8*72*2) + ks*32);
                mma_f16(c8[j], a0, a1, a2, a3, b0, b1);
            }
        }
        #pragma unroll
        for (int j = 0; j < 8; j++) {
            int col = kh0 + 8*j + 2*tig;
            *(float2*)&Ss[(q0w + gid    )*132 + col] = make_float2(c8[j][0], c8[j][1]);
            *(float2*)&Ss[(q0w + gid + 8)*132 + col] = make_float2(c8[j][2], c8[j][3]);
        }
        __syncthreads();

        const float4* srow = (const float4*)&Ss[qrow*132 + seg*32];
        int cb = j0 + seg*32;
        #pragma unroll
        for (int vv = 0; vv < 8; vv++) {
            float4 s4 = srow[vv];
            float m4 = fmaxf(fmaxf(s4.x, s4.y), fmaxf(s4.z, s4.w));
            if (m4 > tmin) {
                tk_push8(s4.x, cb + vv*4 + 0, tv, ti, tmin, tpos);
                tk_push8(s4.y, cb + vv*4 + 1, tv, ti, tmin, tpos);
                tk_push8(s4.z, cb + vv*4 + 2, tv, ti, tmin, tpos);
                tk_push8(s4.w, cb + vv*4 + 3, tv, ti, tmin, tpos);
            }
        }
    }
    __syncthreads();

    float* cval = Ss;
    int*   cidx = (int*)(Ss + 2048);
    #pragma unroll
    for (int p = 0; p < 8; p++) { cval[t*8 + p] = tv[p]; cidx[t*8 + p] = ti[p]; }
    __syncthreads();
    if (t < 64) {
        float fv[16]; int fi[16]; float fmin = -INFINITY; int fpos = 0;
        #pragma unroll
        for (int p = 0; p < 16; p++) { fv[p] = -INFINITY; fi[p] = 0; }
        for (int g = 0; g < 4; g++) {
            int src = t + g*64;
            #pragma unroll
            for (int p = 0; p < 8; p++) {
                tk_push16(cval[src*8 + p], cidx[src*8 + p], fv, fi, fmin, fpos);
            }
        }
        #pragma unroll
        for (int p = 0; p < 16; p++) {
            g_cand[((size_t)h*BNR + q0 + t)*NCAND + p] = fi[p];
        }
    }
}

// --------------- exact fp32 rescore of 16 candidates -> top-8 ---------------
__global__ void __launch_bounds__(256)
rescore_kernel(const float* __restrict__ kmem0)
{
    int e = blockIdx.x * 8 + (threadIdx.x >> 5);
    int lane = threadIdx.x & 31;
    int h = e >> 11, f = e & (BNR - 1);

    float s = -INFINITY;
    int myidx = -1;
    if (lane < NCAND) {
        myidx = g_cand[(size_t)e*NCAND + lane];
        const float* qrow = &g_q[(size_t)f*DIN + h*HD];
        const float* krow = (myidx < MOLD)
            ? &kmem0[((size_t)h*MEMS + myidx + BNR)*HD]
            : &g_k[(size_t)(myidx - MOLD)*DIN + h*HD];
        float acc = 0.0f;
        #pragma unroll
        for (int d4 = 0; d4 < 16; d4++) {
            float4 qv = *(const float4*)&qrow[d4*4];
            float4 kv = *(const float4*)&krow[d4*4];
            acc += qv.x*kv.x + qv.y*kv.y + qv.z*kv.z + qv.w*kv.w;
        }
        s = acc;
    }
    #pragma unroll
    for (int p = 0; p < IPQ; p++) {
        float m = s;
        #pragma unroll
        for (int o = 16; o >= 1; o >>= 1) {
            m = fmaxf(m, __shfl_xor_sync(0xffffffffu, m, o));
        }
        unsigned msk = __ballot_sync(0xffffffffu, s == m);
        int src = __ffs(msk) - 1;
        if (lane == src) {
            g_idx[(size_t)e*IPQ + p] = myidx;
            s = -INFINITY;
        }
    }
}

// --------------------- gather k_m / v_m from idx -----------------------------
__global__ void gather_kernel(const float* __restrict__ kmem0, const float* __restrict__ vmem0)
{
    int e = blockIdx.x * 256 + threadIdx.x;
    int c  = e & 1023;
    int m2 = (e >> 10) & 4095;
    int b  = e >> 22;
    int h = c >> 6, d = c & 63;
    int nq = m2 >> 3, ip = m2 & 7;
    int f = b * NN + nq;
    int row = g_idx[((size_t)h*BNR + f)*IPQ + ip];
    float kv, vv;
    if (row < MOLD) {
        size_t base = ((size_t)h*MEMS + row + BNR)*HD + d;
        kv = kmem0[base]; vv = vmem0[base];
    } else {
        int fl = row - MOLD;
        size_t base = (size_t)fl*DIN + h*HD + d;
        kv = g_k[base]; vv = g_v[base];
    }
    g_km[e] = kv;
    g_vm[e] = vv;
}

// ------------------- flash attention, 64-q tiles, parallel softmax ----------
// QK ownership: 4q x 4j (qg = t>>4, jg = t&15).
// PV ownership: 4q x 4d (qp = t>>4, dp = (t&15)*4) — halves PV smem traffic.
__global__ void __launch_bounds__(256, 2)
flash_attn(const float* __restrict__ Qbuf, const float* __restrict__ Ksrc,
           const float* __restrict__ Vsrc, float* __restrict__ Obuf, int m)
{
    extern __shared__ float sm[];
    float* Qs_ = sm;                // 64*68
    float* Ks_ = Qs_ + 64*68;       // 64*68  (d-major)
    float* Vs_ = Ks_ + 64*68;       // 64*68
    float* Ss_ = Vs_ + 64*68;       // 64*68
    float* mrow = Ss_ + 64*68;
    float* lrow = mrow + 64;
    float* fac  = lrow + 64;

    int t = threadIdx.x;
    int b = blockIdx.z, h = blockIdx.y;
    int f0 = b * NN + blockIdx.x * 64;

    {
        int r = t >> 2, c0 = (t & 3) * 16;
        size_t src = (size_t)(f0 + r)*DIN + h*HD + c0;
        #pragma unroll
        for (int u = 0; u < 4; u++) {
            *(float4*)&Qs_[r*68 + c0 + u*4] = *(const float4*)&Qbuf[src + u*4];
        }
    }
    if (t < 64) { mrow[t] = -INFINITY; lrow[t] = 0.0f; }

    float o[4][4] = {};
    int qg = t >> 4, jg = t & 15;
    int qp = t >> 4, dp = (t & 15) * 4;
    int jrow = t & 63, jc0 = (t >> 6) * 16;
    __syncthreads();

    for (int j0 = 0; j0 < m; j0 += 64) {
        {
            size_t src = ((size_t)b*m + j0 + jrow)*DIN + h*HD + jc0;
            #pragma unroll
            for (int u = 0; u < 4; u++) {
                float4 kv = *(const float4*)&Ksrc[src + u*4];
                Ks_[(jc0 + u*4 + 0)*68 + jrow] = kv.x;
                Ks_[(jc0 + u*4 + 1)*68 + jrow] = kv.y;
                Ks_[(jc0 + u*4 + 2)*68 + jrow] = kv.z;
                Ks_[(jc0 + u*4 + 3)*68 + jrow] = kv.w;
            }
            #pragma unroll
            for (int u = 0; u < 4; u++) {
                *(float4*)&Vs_[jrow*68 + jc0 + u*4] = *(const float4*)&Vsrc[src + u*4];
            }
        }
        __syncthreads();

        float acc[4][4] = {};
        #pragma unroll
        for (int d4 = 0; d4 < 16; d4++) {
            float4 a0 = *(const float4*)&Qs_[(qg*4+0)*68 + d4*4];
            float4 a1 = *(const float4*)&Qs_[(qg*4+1)*68 + d4*4];
            float4 a2 = *(const float4*)&Qs_[(qg*4+2)*68 + d4*4];
            float4 a3 = *(const float4*)&Qs_[(qg*4+3)*68 + d4*4];
            #pragma unroll
            for (int dd = 0; dd < 4; dd++) {
                float4 bv = *(const float4*)&Ks_[(d4*4+dd)*68 + jg*4];
                float x0 = ((const float*)&a0)[dd];
                float x1 = ((const float*)&a1)[dd];
                float x2 = ((const float*)&a2)[dd];
                float x3 = ((const float*)&a3)[dd];
                acc[0][0] += x0*bv.x; acc[0][1] += x0*bv.y; acc[0][2] += x0*bv.z; acc[0][3] += x0*bv.w;
                acc[1][0] += x1*bv.x; acc[1][1] += x1*bv.y; acc[1][2] += x1*bv.z; acc[1][3] += x1*bv.w;
                acc[2][0] += x2*bv.x; acc[2][1] += x2*bv.y; acc[2][2] += x2*bv.z; acc[2][3] += x2*bv.w;
                acc[3][0] += x3*bv.x; acc[3][1] += x3*bv.y; acc[3][2] += x3*bv.z; acc[3][3] += x3*bv.w;
            }
        }

        #pragma unroll
        for (int i = 0; i < 4; i++) {
            int row = qg*4 + i;
            float s0 = acc[i][0]*SCALE, s1 = acc[i][1]*SCALE;
            float s2 = acc[i][2]*SCALE, s3 = acc[i][3]*SCALE;
            float rm = fmaxf(fmaxf(s0, s1), fmaxf(s2, s3));
            #pragma unroll
            for (int wdt = 1; wdt < 16; wdt <<= 1) {
                rm = fmaxf(rm, __shfl_xor_sync(0xffffffffu, rm, wdt, 16));
            }
            float mo = mrow[row];
            float mc = fmaxf(mo, rm);
            float fsc = __expf(mo - mc);
            float e0 = __expf(s0 - mc), e1 = __expf(s1 - mc);
            float e2 = __expf(s2 - mc), e3 = __expf(s3 - mc);
            float rs = e0 + e1 + e2 + e3;
            #pragma unroll
            for (int wdt = 1; wdt < 16; wdt <<= 1) {
                rs += __shfl_xor_sync(0xffffffffu, rs, wdt, 16);
            }
            float lold = lrow[row];
            mrow[row] = mc;
            lrow[row] = lold * fsc + rs;
            fac[row]  = fsc;
            *(float4*)&Ss_[row*68 + jg*4] = make_float4(e0, e1, e2, e3);
        }
        __syncthreads();

        // PV: 4q x 4d per thread; p scalar broadcast, V one LDS.128 per j
        float f0q = fac[qp*4+0], f1q = fac[qp*4+1];
        float f2q = fac[qp*4+2], f3q = fac[qp*4+3];
        #pragma unroll
        for (int u = 0; u < 4; u++) { o[0][u] *= f0q; o[1][u] *= f1q; o[2][u] *= f2q; o[3][u] *= f3q; }
        for (int j = 0; j < 64; j++) {
            float4 vv = *(const float4*)&Vs_[j*68 + dp];
            float p0 = Ss_[(qp*4+0)*68 + j];
            float p1 = Ss_[(qp*4+1)*68 + j];
            float p2 = Ss_[(qp*4+2)*68 + j];
            float p3 = Ss_[(qp*4+3)*68 + j];
            o[0][0] += p0*vv.x; o[0][1] += p0*vv.y; o[0][2] += p0*vv.z; o[0][3] += p0*vv.w;
            o[1][0] += p1*vv.x; o[1][1] += p1*vv.y; o[1][2] += p1*vv.z; o[1][3] += p1*vv.w;
            o[2][0] += p2*vv.x; o[2][1] += p2*vv.y; o[2][2] += p2*vv.z; o[2][3] += p2*vv.w;
            o[3][0] += p3*vv.x; o[3][1] += p3*vv.y; o[3][2] += p3*vv.z; o[3][3] += p3*vv.w;
        }
        __syncthreads();
    }
    #pragma unroll
    for (int i = 0; i < 4; i++) {
        float inv = 1.0f / lrow[qp*4 + i];
        size_t dst = (size_t)(f0 + qp*4 + i)*DOUT + h*HD + dp;
        *(float4*)&Obuf[dst] = make_float4(o[i][0]*inv, o[i][1]*inv, o[i][2]*inv, o[i][3]*inv);
    }
}

// ---------------------------- gate combine -----------------------------------
__global__ void combine_kernel(float* __restrict__ out)
{
    int e = blockIdx.x * 256 + threadIdx.x;
    float w = g_w[e];
    out[e] = w * g_c1[e] + (1.0f - w) * g_c2[e];
}

// ------------------------------- launch --------------------------------------
extern "C" void kernel_launch(void* const* d_in, const int* in_sizes, int n_in,
                              void* d_out, int out_size)
{
    const float* x     = (const float*)d_in[0];
    const float* Wq    = (const float*)d_in[1];
    const float* Wk    = (const float*)d_in[2];
    const float* Wv    = (const float*)d_in[3];
    const float* Ww    = (const float*)d_in[4];
    const float* Wo    = (const float*)d_in[5];
    const float* bo    = (const float*)d_in[6];
    const float* kmem0 = (const float*)d_in[7];
    const float* vmem0 = (const float*)d_in[8];
    float* out = (float*)d_out;

    float *q, *k, *v, *w, *ao, *aom, *c1, *c2, *km, *vm;
    cudaGetSymbolAddress((void**)&q,   g_q);
    cudaGetSymbolAddress((void**)&k,   g_k);
    cudaGetSymbolAddress((void**)&v,   g_v);
    cudaGetSymbolAddress((void**)&w,   g_w);
    cudaGetSymbolAddress((void**)&ao,  g_ao);
    cudaGetSymbolAddress((void**)&aom, g_aom);
    cudaGetSymbolAddress((void**)&c1,  g_c1);
    cudaGetSymbolAddress((void**)&c2,  g_c2);
    cudaGetSymbolAddress((void**)&km,  g_km);
    cudaGetSymbolAddress((void**)&vm,  g_vm);

    const int SIMS_SMEM  = (64*72 + 128*72)*2 + 64*132*4;   // 61440
    const int FLASH_SMEM = (4*64*68 + 3*64)*4;              // 70400
    cudaFuncSetAttribute(sims_topk,  cudaFuncAttributeMaxDynamicSharedMemorySize, SIMS_SMEM);
    cudaFuncSetAttribute(flash_attn, cudaFuncAttributeMaxDynamicSharedMemorySize, FLASH_SMEM);

    dim3 gemm_grid(DOUT/128, BNR/128);

    // order chosen so sims_topk is the 6th launch (ncu -s 5 -c 1 captures it)
    sgemm_abt<<<gemm_grid, 256>>>(x, Wq, q, BNR, DIN,  DIN, 0, 0);   // 1
    sgemm_abt<<<gemm_grid, 256>>>(x, Wk, k, BNR, DIN,  DIN, 0, 0);   // 2
    convert_q<<<(H*BNR*HD)/256, 256>>>();                            // 3
    convert_k<<<(H*MEMS*HD)/256, 256>>>(kmem0);                      // 4
    sgemm_abt<<<gemm_grid, 256>>>(x, Wv, v, BNR, DOUT, DIN, 0, 0);   // 5
    sims_topk<<<dim3(BNR/64, H), 256, SIMS_SMEM>>>();                // 6 <- profiled
    sgemm_abt<<<gemm_grid, 256>>>(x, Ww, w, BNR, DOUT, DIN, 0, 1);   // 7
    flash_attn<<<dim3(NN/64, H, BB), 256, FLASH_SMEM>>>(q, k, v, ao, NN);        // 8
    rescore_kernel<<<(H*BNR)/8, 256>>>(kmem0);                       // 9
    gather_kernel<<<(BB*NN*IPQ*DIN)/256, 256>>>(kmem0, vmem0);       // 10
    flash_attn<<<dim3(NN/64, H, BB), 256, FLASH_SMEM>>>(q, km, vm, aom, NN*IPQ); // 11
    sgemm_abt<<<gemm_grid, 256>>>(ao,  Wo, c1, BNR, DOUT, DOUT, bo, 0);          // 12
    sgemm_abt<<<gemm_grid, 256>>>(aom, Wo, c2, BNR, DOUT, DOUT, bo, 0);          // 13
    combine_kernel<<<(BNR*DOUT)/256, 256>>>(out);                    // 14
}

// round 12
// speedup vs baseline: 3.1039x; 1.1194x over previous
#include <cuda_runtime.h>
#include <cuda_fp16.h>
#include <cstdint>
#include <cstdio>
#include <math.h>

typedef unsigned int u32;

#define H    16
#define HD   64
#define MEMS 32768
#define IPQ  8
#define NCAND 16
#define BB   4
#define NN   512
#define DIN  1024
#define DOUT 1024
#define BNR  (BB*NN)
#define MOLD (MEMS - BNR)
#define SCALE 0.125f

// ------------------------- scratch (device globals) -------------------------
__device__ float g_q  [BNR*DIN];
__device__ float g_k  [BNR*DIN];
__device__ float g_v  [BNR*DOUT];
__device__ float g_w  [BNR*DOUT];
__device__ float g_ao [BNR*DOUT];
__device__ float g_aom[BNR*DOUT];
__device__ float g_c1 [BNR*DOUT];
__device__ float g_c2 [BNR*DOUT];
__device__ float g_km [(size_t)BB*(NN*IPQ)*DIN];
__device__ float g_vm [(size_t)BB*(NN*IPQ)*DOUT];
__device__ int   g_idx [H*BNR*IPQ];
__device__ int   g_cand[(size_t)H*BNR*NCAND];
__device__ __half g_qhi[(size_t)H*BNR*HD];
__device__ __half g_khi[(size_t)H*MEMS*HD];
// split planes for tensor GEMM
__device__ __half g_xhi[(size_t)BNR*DIN],  g_xlo[(size_t)BNR*DIN];
__device__ __half g_Whi[(size_t)5*DIN*DOUT], g_Wlo[(size_t)5*DIN*DOUT]; // Wq,Wk,Wv,Ww,Wo
__device__ __half g_ahi[(size_t)BNR*DOUT], g_alo[(size_t)BNR*DOUT];     // reused ao then aom

// ------------------------- helpers -------------------------
__device__ __forceinline__ u32 smem_u32(const void* p) {
    return (u32)__cvta_generic_to_shared(p);
}
__device__ __forceinline__ void ldsm_x4(u32 &r0, u32 &r1, u32 &r2, u32 &r3, u32 addr) {
    asm volatile("ldmatrix.sync.aligned.m8n8.x4.shared.b16 {%0,%1,%2,%3}, [%4];"
        : "=r"(r0), "=r"(r1), "=r"(r2), "=r"(r3) : "r"(addr));
}
__device__ __forceinline__ void ldsm_x2(u32 &r0, u32 &r1, u32 addr) {
    asm volatile("ldmatrix.sync.aligned.m8n8.x2.shared.b16 {%0,%1}, [%2];"
        : "=r"(r0), "=r"(r1) : "r"(addr));
}
__device__ __forceinline__ void mma_f16(float* c, u32 a0, u32 a1, u32 a2, u32 a3,
                                        u32 b0, u32 b1) {
    asm volatile("mma.sync.aligned.m16n8k16.row.col.f32.f16.f16.f32 "
        "{%0,%1,%2,%3}, {%4,%5,%6,%7}, {%8,%9}, {%0,%1,%2,%3};"
        : "+f"(c[0]), "+f"(c[1]), "+f"(c[2]), "+f"(c[3])
        : "r"(a0), "r"(a1), "r"(a2), "r"(a3), "r"(b0), "r"(b1));
}

// ------------------- fp32 -> fp16 hi/lo split ------------------------------
__global__ void split_f32(const float* __restrict__ src, __half* __restrict__ hi,
                          __half* __restrict__ lo)
{
    int e = blockIdx.x * 256 + threadIdx.x;
    float val = src[e];
    __half h = __float2half_rn(val);
    hi[e] = h;
    lo[e] = __float2half_rn(val - __half2float(h));
}

// ------------------- split-fp16 HMMA GEMM: C = A * B^T ----------------------
// A [2048,K] planes, B [1024,K] planes, C [2048,1024]. 128x128 block, 8 warps,
// warp tile 32x64 (2 x m16 strips, 8 x n8 tiles). K-chunk 64.
__global__ void __launch_bounds__(256)
hgemm_abt(const __half* __restrict__ Ahi, const __half* __restrict__ Alo,
          const __half* __restrict__ Bhi, const __half* __restrict__ Blo,
          float* __restrict__ C, int K,
          const float* __restrict__ bias, int do_sigmoid)
{
    extern __shared__ __half hsm[];
    __half* Ah = hsm;                 // [128][72]
    __half* Al = Ah + 128*72;
    __half* Bh = Al + 128*72;
    __half* Bl = Bh + 128*72;
    const u32 ALO_OFF = 128*72*2;     // bytes Ah->Al
    const u32 BLO_OFF = 128*72*2;     // bytes Bh->Bl

    int t = threadIdx.x;
    int lane = t & 31, warp = t >> 5;
    int row0 = blockIdx.y * 128, col0 = blockIdx.x * 128;
    int mrow0 = (warp >> 1) * 32;     // warp M strip (4 strips of 32)
    int ncol0 = (warp & 1) * 64;      // warp N half

    float acc[2][8][4] = {};

    u32 a_base = smem_u32(&Ah[(mrow0 + (lane & 15))*72 + ((lane >> 4) & 1)*8]);
    u32 b_base = smem_u32(&Bh[(ncol0 + (lane & 7))*72 + ((lane >> 3) & 1)*8]);

    int lr = t >> 1, lc0 = (t & 1) * 32;

    for (int k0 = 0; k0 < K; k0 += 64) {
        // load 128x64 tiles of all four planes
        {
            size_t asrc = (size_t)(row0 + lr)*K + k0 + lc0;
            *(uint4*)&Ah[lr*72 + lc0     ] = *(const uint4*)&Ahi[asrc];
            *(uint4*)&Ah[lr*72 + lc0 + 8 ] = *(const uint4*)&Ahi[asrc + 8];
            *(uint4*)&Ah[lr*72 + lc0 + 16] = *(const uint4*)&Ahi[asrc + 16];
            *(uint4*)&Ah[lr*72 + lc0 + 24] = *(const uint4*)&Ahi[asrc + 24];
            *(uint4*)&Al[lr*72 + lc0     ] = *(const uint4*)&Alo[asrc];
            *(uint4*)&Al[lr*72 + lc0 + 8 ] = *(const uint4*)&Alo[asrc + 8];
            *(uint4*)&Al[lr*72 + lc0 + 16] = *(const uint4*)&Alo[asrc + 16];
            *(uint4*)&Al[lr*72 + lc0 + 24] = *(const uint4*)&Alo[asrc + 24];
            size_t bsrc = (size_t)(col0 + lr)*K + k0 + lc0;
            *(uint4*)&Bh[lr*72 + lc0     ] = *(const uint4*)&Bhi[bsrc];
            *(uint4*)&Bh[lr*72 + lc0 + 8 ] = *(const uint4*)&Bhi[bsrc + 8];
            *(uint4*)&Bh[lr*72 + lc0 + 16] = *(const uint4*)&Bhi[bsrc + 16];
            *(uint4*)&Bh[lr*72 + lc0 + 24] = *(const uint4*)&Bhi[bsrc + 24];
            *(uint4*)&Bl[lr*72 + lc0     ] = *(const uint4*)&Blo[bsrc];
            *(uint4*)&Bl[lr*72 + lc0 + 8 ] = *(const uint4*)&Blo[bsrc + 8];
            *(uint4*)&Bl[lr*72 + lc0 + 16] = *(const uint4*)&Blo[bsrc + 16];
            *(uint4*)&Bl[lr*72 + lc0 + 24] = *(const uint4*)&Blo[bsrc + 24];
        }
        __syncthreads();

        #pragma unroll
        for (int kc = 0; kc < 4; kc++) {
            u32 ah[2][4], al[2][4];
            #pragma unroll
            for (int mi = 0; mi < 2; mi++) {
                u32 aoff = a_base + (u32)mi*(16*72*2) + kc*32;
                ldsm_x4(ah[mi][0], ah[mi][1], ah[mi][2], ah[mi][3], aoff);
                ldsm_x4(al[mi][0], al[mi][1], al[mi][2], al[mi][3], aoff + ALO_OFF);
            }
            #pragma unroll
            for (int nj = 0; nj < 8; nj++) {
                u32 boff = b_base + (u32)nj*(8*72*2) + kc*32;
                u32 bh0, bh1, bl0, bl1;
                ldsm_x2(bh0, bh1, boff);
                ldsm_x2(bl0, bl1, boff + BLO_OFF);
                #pragma unroll
                for (int mi = 0; mi < 2; mi++) {
                    mma_f16(acc[mi][nj], ah[mi][0], ah[mi][1], ah[mi][2], ah[mi][3], bh0, bh1);
                    mma_f16(acc[mi][nj], ah[mi][0], ah[mi][1], ah[mi][2], ah[mi][3], bl0, bl1);
                    mma_f16(acc[mi][nj], al[mi][0], al[mi][1], al[mi][2], al[mi][3], bh0, bh1);
                }
            }
        }
        __syncthreads();
    }

    // epilogue: frag (gid, tig) -> rows gid, gid+8; cols 2*tig, 2*tig+1
    int gid = lane >> 2, tig = lane & 3;
    #pragma unroll
    for (int mi = 0; mi < 2; mi++) {
        #pragma unroll
        for (int nj = 0; nj < 8; nj++) {
            int r0 = row0 + mrow0 + mi*16 + gid;
            int cc = col0 + ncol0 + nj*8 + 2*tig;
            #pragma unroll
            for (int hh = 0; hh < 2; hh++) {
                int r = r0 + hh*8;
                float v0 = acc[mi][nj][hh*2+0];
                float v1 = acc[mi][nj][hh*2+1];
                if (bias) { v0 += bias[cc]; v1 += bias[cc+1]; }
                if (do_sigmoid) {
                    v0 = 1.0f / (1.0f + __expf(-v0));
                    v1 = 1.0f / (1.0f + __expf(-v1));
                }
                *(float2*)&C[(size_t)r * DOUT + cc] = make_float2(v0, v1);
            }
        }
    }
}

// ------------------- fp16 hi-plane precompute (sims) ------------------------
__global__ void convert_k(const float* __restrict__ kmem0)
{
    int e = blockIdx.x * 256 + threadIdx.x;
    int d = e & 63;
    int j = (e >> 6) & (MEMS - 1);
    int h = e >> 21;
    float val = (j < MOLD)
        ? kmem0[((size_t)h*MEMS + j + BNR)*HD + d]
        : g_k[(size_t)(j - MOLD)*DIN + h*HD + d];
    g_khi[e] = __float2half_rn(val);
}

__global__ void convert_q()
{
    int e = blockIdx.x * 256 + threadIdx.x;
    int d = e & 63;
    int r = (e >> 6) & (BNR - 1);
    int h = e >> 17;
    g_qhi[e] = __float2half_rn(g_q[(size_t)r*DIN + h*HD + d]);
}

// ------------------------- top-K push helpers -------------------------
__device__ __forceinline__ void tk_push8(float s, int id, float* tv, int* ti,
                                         float &tmin, int &tpos) {
    if (s > tmin) {
        tv[tpos] = s; ti[tpos] = id;
        tmin = tv[0]; tpos = 0;
        #pragma unroll
        for (int p = 1; p < 8; p++) {
            if (tv[p] < tmin) { tmin = tv[p]; tpos = p; }
        }
    }
}
__device__ __forceinline__ void tk_push16(float s, int id, float* tv, int* ti,
                                          float &tmin, int &tpos) {
    if (s > tmin) {
        tv[tpos] = s; ti[tpos] = id;
        tmin = tv[0]; tpos = 0;
        #pragma unroll
        for (int p = 1; p < 16; p++) {
            if (tv[p] < tmin) { tmin = tv[p]; tpos = p; }
        }
    }
}

// --------------- coarse sims + top-16 candidates via fp16 HMMA -------------
__global__ void __launch_bounds__(256, 2)
sims_topk()
{
    extern __shared__ char smraw[];
    __half* Qh = (__half*)smraw;                  // [64][72]
    __half* Kh = Qh + 64*72;                      // [128][72]
    float* Ss = (float*)(smraw + (64*72 + 128*72)*2);   // [64][132]

    int t = threadIdx.x;
    int h = blockIdx.y;
    int q0 = blockIdx.x * 64;
    int lane = t & 31, warp = t >> 5;
    int gid = lane >> 2, tig = lane & 3;

    {
        int r = t >> 2, c0 = (t & 3) * 16;
        size_t src = ((size_t)h*BNR + q0 + r)*HD + c0;
        *(uint4*)&Qh[r*72 + c0    ] = *(const uint4*)&g_qhi[src];
        *(uint4*)&Qh[r*72 + c0 + 8] = *(const uint4*)&g_qhi[src + 8];
    }

    float tv[8]; int ti[8];
    #pragma unroll
    for (int p = 0; p < 8; p++) { tv[p] = -INFINITY; ti[p] = 0; }
    float tmin = -INFINITY; int tpos = 0;

    int q0w = (warp >> 1) * 16;
    int kh0 = (warp & 1) * 64;

    u32 a_base = smem_u32(&Qh[(q0w + (lane & 15))*72 + ((lane >> 4) & 1)*8]);
    u32 b_base = smem_u32(&Kh[(kh0 + (lane & 7))*72 + ((lane >> 3) & 1)*8]);

    int qrow = t & 63, seg = t >> 6;
    int kr = t >> 1, kc0 = (t & 1) * 32;

    for (int tile = 0; tile < MEMS/128; tile++) {
        int j0 = tile * 128;
        {
            size_t src = ((size_t)h*MEMS + j0 + kr)*HD + kc0;
            #pragma unroll
            for (int uu = 0; uu < 4; uu++) {
                *(uint4*)&Kh[kr*72 + kc0 + uu*8] = *(const uint4*)&g_khi[src + uu*8];
            }
        }
        __syncthreads();

        float c8[8][4] = {};
        #pragma unroll
        for (int ks = 0; ks < 4; ks++) {
            u32 a0, a1, a2, a3;
            ldsm_x4(a0, a1, a2, a3, a_base + ks*32);
            #pragma unroll
            for (int j = 0; j < 8; j++) {
                u32 b0, b1;
                ldsm_x2(b0, b1, b_base + (u32)j*(8*72*2) + ks*32);
                mma_f16(c8[j], a0, a1, a2, a3, b0, b1);
            }
        }
        #pragma unroll
        for (int j = 0; j < 8; j++) {
            int col = kh0 + 8*j + 2*tig;
            *(float2*)&Ss[(q0w + gid    )*132 + col] = make_float2(c8[j][0], c8[j][1]);
            *(float2*)&Ss[(q0w + gid + 8)*132 + col] = make_float2(c8[j][2], c8[j][3]);
        }
        __syncthreads();

        const float4* srow = (const float4*)&Ss[qrow*132 + seg*32];
        int cb = j0 + seg*32;
        #pragma unroll
        for (int vv = 0; vv < 8; vv++) {
            float4 s4 = srow[vv];
            float m4 = fmaxf(fmaxf(s4.x, s4.y), fmaxf(s4.z, s4.w));
            if (m4 > tmin) {
                tk_push8(s4.x, cb + vv*4 + 0, tv, ti, tmin, tpos);
                tk_push8(s4.y, cb + vv*4 + 1, tv, ti, tmin, tpos);
                tk_push8(s4.z, cb + vv*4 + 2, tv, ti, tmin, tpos);
                tk_push8(s4.w, cb + vv*4 + 3, tv, ti, tmin, tpos);
            }
        }
    }
    __syncthreads();

    float* cval = Ss;
    int*   cidx = (int*)(Ss + 2048);
    #pragma unroll
    for (int p = 0; p < 8; p++) { cval[t*8 + p] = tv[p]; cidx[t*8 + p] = ti[p]; }
    __syncthreads();
    if (t < 64) {
        float fv[16]; int fi[16]; float fmin = -INFINITY; int fpos = 0;
        #pragma unroll
        for (int p = 0; p < 16; p++) { fv[p] = -INFINITY; fi[p] = 0; }
        for (int g = 0; g < 4; g++) {
            int src = t + g*64;
            #pragma unroll
            for (int p = 0; p < 8; p++) {
                tk_push16(cval[src*8 + p], cidx[src*8 + p], fv, fi, fmin, fpos);
            }
        }
        #pragma unroll
        for (int p = 0; p < 16; p++) {
            g_cand[((size_t)h*BNR + q0 + t)*NCAND + p] = fi[p];
        }
    }
}

// --------------- exact fp32 rescore of 16 candidates -> top-8 ---------------
__global__ void __launch_bounds__(256)
rescore_kernel(const float* __restrict__ kmem0)
{
    int e = blockIdx.x * 8 + (threadIdx.x >> 5);
    int lane = threadIdx.x & 31;
    int h = e >> 11, f = e & (BNR - 1);

    float s = -INFINITY;
    int myidx = -1;
    if (lane < NCAND) {
        myidx = g_cand[(size_t)e*NCAND + lane];
        const float* qrow = &g_q[(size_t)f*DIN + h*HD];
        const float* krow = (myidx < MOLD)
            ? &kmem0[((size_t)h*MEMS + myidx + BNR)*HD]
            : &g_k[(size_t)(myidx - MOLD)*DIN + h*HD];
        float acc = 0.0f;
        #pragma unroll
        for (int d4 = 0; d4 < 16; d4++) {
            float4 qv = *(const float4*)&qrow[d4*4];
            float4 kv = *(const float4*)&krow[d4*4];
            acc += qv.x*kv.x + qv.y*kv.y + qv.z*kv.z + qv.w*kv.w;
        }
        s = acc;
    }
    #pragma unroll
    for (int p = 0; p < IPQ; p++) {
        float m = s;
        #pragma unroll
        for (int o = 16; o >= 1; o >>= 1) {
            m = fmaxf(m, __shfl_xor_sync(0xffffffffu, m, o));
        }
        unsigned msk = __ballot_sync(0xffffffffu, s == m);
        int src = __ffs(msk) - 1;
        if (lane == src) {
            g_idx[(size_t)e*IPQ + p] = myidx;
            s = -INFINITY;
        }
    }
}

// --------------------- gather k_m / v_m from idx -----------------------------
__global__ void gather_kernel(const float* __restrict__ kmem0, const float* __restrict__ vmem0)
{
    int e = blockIdx.x * 256 + threadIdx.x;
    int c  = e & 1023;
    int m2 = (e >> 10) & 4095;
    int b  = e >> 22;
    int h = c >> 6, d = c & 63;
    int nq = m2 >> 3, ip = m2 & 7;
    int f = b * NN + nq;
    int row = g_idx[((size_t)h*BNR + f)*IPQ + ip];
    float kv, vv;
    if (row < MOLD) {
        size_t base = ((size_t)h*MEMS + row + BNR)*HD + d;
        kv = kmem0[base]; vv = vmem0[base];
    } else {
        int fl = row - MOLD;
        size_t base = (size_t)fl*DIN + h*HD + d;
        kv = g_k[base]; vv = g_v[base];
    }
    g_km[e] = kv;
    g_vm[e] = vv;
}

// ------------------- flash attention, 64-q tiles, parallel softmax ----------
__global__ void __launch_bounds__(256, 2)
flash_attn(const float* __restrict__ Qbuf, const float* __restrict__ Ksrc,
           const float* __restrict__ Vsrc, float* __restrict__ Obuf, int m)
{
    extern __shared__ float sm[];
    float* Qs_ = sm;                // 64*68
    float* Ks_ = Qs_ + 64*68;       // 64*68  (d-major)
    float* Vs_ = Ks_ + 64*68;       // 64*68
    float* Ss_ = Vs_ + 64*68;       // 64*68
    float* mrow = Ss_ + 64*68;
    float* lrow = mrow + 64;
    float* fac  = lrow + 64;

    int t = threadIdx.x;
    int b = blockIdx.z, h = blockIdx.y;
    int f0 = b * NN + blockIdx.x * 64;

    {
        int r = t >> 2, c0 = (t & 3) * 16;
        size_t src = (size_t)(f0 + r)*DIN + h*HD + c0;
        #pragma unroll
        for (int u = 0; u < 4; u++) {
            *(float4*)&Qs_[r*68 + c0 + u*4] = *(const float4*)&Qbuf[src + u*4];
        }
    }
    if (t < 64) { mrow[t] = -INFINITY; lrow[t] = 0.0f; }

    float o[4][4] = {};
    int qg = t >> 4, jg = t & 15;
    int qp = t >> 4, dp = (t & 15) * 4;
    int jrow = t & 63, jc0 = (t >> 6) * 16;
    __syncthreads();

    for (int j0 = 0; j0 < m; j0 += 64) {
        {
            size_t src = ((size_t)b*m + j0 + jrow)*DIN + h*HD + jc0;
            #pragma unroll
            for (int u = 0; u < 4; u++) {
                float4 kv = *(const float4*)&Ksrc[src + u*4];
                Ks_[(jc0 + u*4 + 0)*68 + jrow] = kv.x;
                Ks_[(jc0 + u*4 + 1)*68 + jrow] = kv.y;
                Ks_[(jc0 + u*4 + 2)*68 + jrow] = kv.z;
                Ks_[(jc0 + u*4 + 3)*68 + jrow] = kv.w;
            }
            #pragma unroll
            for (int u = 0; u < 4; u++) {
                *(float4*)&Vs_[jrow*68 + jc0 + u*4] = *(const float4*)&Vsrc[src + u*4];
            }
        }
        __syncthreads();

        float acc[4][4] = {};
        #pragma unroll
        for (int d4 = 0; d4 < 16; d4++) {
            float4 a0 = *(const float4*)&Qs_[(qg*4+0)*68 + d4*4];
            float4 a1 = *(const float4*)&Qs_[(qg*4+1)*68 + d4*4];
            float4 a2 = *(const float4*)&Qs_[(qg*4+2)*68 + d4*4];
            float4 a3 = *(const float4*)&Qs_[(qg*4+3)*68 + d4*4];
            #pragma unroll
            for (int dd = 0; dd < 4; dd++) {
                float4 bv = *(const float4*)&Ks_[(d4*4+dd)*68 + jg*4];
                float x0 = ((const float*)&a0)[dd];
                float x1 = ((const float*)&a1)[dd];
                float x2 = ((const float*)&a2)[dd];
                float x3 = ((const float*)&a3)[dd];
                acc[0][0] += x0*bv.x; acc[0][1] += x0*bv.y; acc[0][2] += x0*bv.z; acc[0][3] += x0*bv.w;
                acc[1][0] += x1*bv.x; acc[1][1] += x1*bv.y; acc[1][2] += x1*bv.z; acc[1][3] += x1*bv.w;
                acc[2][0] += x2*bv.x; acc[2][1] += x2*bv.y; acc[2][2] += x2*bv.z; acc[2][3] += x2*bv.w;
                acc[3][0] += x3*bv.x; acc[3][1] += x3*bv.y; acc[3][2] += x3*bv.z; acc[3][3] += x3*bv.w;
            }
        }

        #pragma unroll
        for (int i = 0; i < 4; i++) {
            int row = qg*4 + i;
            float s0 = acc[i][0]*SCALE, s1 = acc[i][1]*SCALE;
            float s2 = acc[i][2]*SCALE, s3 = acc[i][3]*SCALE;
            float rm = fmaxf(fmaxf(s0, s1), fmaxf(s2, s3));
            #pragma unroll
            for (int wdt = 1; wdt < 16; wdt <<= 1) {
                rm = fmaxf(rm, __shfl_xor_sync(0xffffffffu, rm, wdt, 16));
            }
            float mo = mrow[row];
            float mc = fmaxf(mo, rm);
            float fsc = __expf(mo - mc);
            float e0 = __expf(s0 - mc), e1 = __expf(s1 - mc);
            float e2 = __expf(s2 - mc), e3 = __expf(s3 - mc);
            float rs = e0 + e1 + e2 + e3;
            #pragma unroll
            for (int wdt = 1; wdt < 16; wdt <<= 1) {
                rs += __shfl_xor_sync(0xffffffffu, rs, wdt, 16);
            }
            float lold = lrow[row];
            mrow[row] = mc;
            lrow[row] = lold * fsc + rs;
            fac[row]  = fsc;
            *(float4*)&Ss_[row*68 + jg*4] = make_float4(e0, e1, e2, e3);
        }
        __syncthreads();

        float f0q = fac[qp*4+0], f1q = fac[qp*4+1];
        float f2q = fac[qp*4+2], f3q = fac[qp*4+3];
        #pragma unroll
        for (int u = 0; u < 4; u++) { o[0][u] *= f0q; o[1][u] *= f1q; o[2][u] *= f2q; o[3][u] *= f3q; }
        for (int j = 0; j < 64; j++) {
            float4 vv = *(const float4*)&Vs_[j*68 + dp];
            float p0 = Ss_[(qp*4+0)*68 + j];
            float p1 = Ss_[(qp*4+1)*68 + j];
            float p2 = Ss_[(qp*4+2)*68 + j];
            float p3 = Ss_[(qp*4+3)*68 + j];
            o[0][0] += p0*vv.x; o[0][1] += p0*vv.y; o[0][2] += p0*vv.z; o[0][3] += p0*vv.w;
            o[1][0] += p1*vv.x; o[1][1] += p1*vv.y; o[1][2] += p1*vv.z; o[1][3] += p1*vv.w;
            o[2][0] += p2*vv.x; o[2][1] += p2*vv.y; o[2][2] += p2*vv.z; o[2][3] += p2*vv.w;
            o[3][0] += p3*vv.x; o[3][1] += p3*vv.y; o[3][2] += p3*vv.z; o[3][3] += p3*vv.w;
        }
        __syncthreads();
    }
    #pragma unroll
    for (int i = 0; i < 4; i++) {
        float inv = 1.0f / lrow[qp*4 + i];
        size_t dst = (size_t)(f0 + qp*4 + i)*DOUT + h*HD + dp;
        *(float4*)&Obuf[dst] = make_float4(o[i][0]*inv, o[i][1]*inv, o[i][2]*inv, o[i][3]*inv);
    }
}

// ---------------------------- gate combine -----------------------------------
__global__ void combine_kernel(float* __restrict__ out)
{
    int e = blockIdx.x * 256 + threadIdx.x;
    float w = g_w[e];
    out[e] = w * g_c1[e] + (1.0f - w) * g_c2[e];
}

// ------------------------------- launch --------------------------------------
extern "C" void kernel_launch(void* const* d_in, const int* in_sizes, int n_in,
                              void* d_out, int out_size)
{
    const float* x     = (const float*)d_in[0];
    const float* Wq    = (const float*)d_in[1];
    const float* Wk    = (const float*)d_in[2];
    const float* Wv    = (const float*)d_in[3];
    const float* Ww    = (const float*)d_in[4];
    const float* Wo    = (const float*)d_in[5];
    const float* bo    = (const float*)d_in[6];
    const float* kmem0 = (const float*)d_in[7];
    const float* vmem0 = (const float*)d_in[8];
    float* out = (float*)d_out;

    float *q, *k, *v, *w, *ao, *aom, *c1, *c2, *km, *vm;
    cudaGetSymbolAddress((void**)&q,   g_q);
    cudaGetSymbolAddress((void**)&k,   g_k);
    cudaGetSymbolAddress((void**)&v,   g_v);
    cudaGetSymbolAddress((void**)&w,   g_w);
    cudaGetSymbolAddress((void**)&ao,  g_ao);
    cudaGetSymbolAddress((void**)&aom, g_aom);
    cudaGetSymbolAddress((void**)&c1,  g_c1);
    cudaGetSymbolAddress((void**)&c2,  g_c2);
    cudaGetSymbolAddress((void**)&km,  g_km);
    cudaGetSymbolAddress((void**)&vm,  g_vm);
    __half *xhi, *xlo, *Whi, *Wlo, *ahi, *alo;
    cudaGetSymbolAddress((void**)&xhi, g_xhi);
    cudaGetSymbolAddress((void**)&xlo, g_xlo);
    cudaGetSymbolAddress((void**)&Whi, g_Whi);
    cudaGetSymbolAddress((void**)&Wlo, g_Wlo);
    cudaGetSymbolAddress((void**)&ahi, g_ahi);
    cudaGetSymbolAddress((void**)&alo, g_alo);

    const int SIMS_SMEM  = (64*72 + 128*72)*2 + 64*132*4;   // 61440
    const int FLASH_SMEM = (4*64*68 + 3*64)*4;              // 70400
    const int HGEMM_SMEM = 4*128*72*2;                      // 73728
    cudaFuncSetAttribute(sims_topk,  cudaFuncAttributeMaxDynamicSharedMemorySize, SIMS_SMEM);
    cudaFuncSetAttribute(flash_attn, cudaFuncAttributeMaxDynamicSharedMemorySize, FLASH_SMEM);
    cudaFuncSetAttribute(hgemm_abt,  cudaFuncAttributeMaxDynamicSharedMemorySize, HGEMM_SMEM);

    const int WSZ = DIN*DOUT;   // 1M elements per weight matrix
    dim3 hgrid(DOUT/128, BNR/128);   // (8, 16)

    // split x and all 5 weight matrices into fp16 hi/lo planes
    split_f32<<<(BNR*DIN)/256, 256>>>(x,  xhi, xlo);
    split_f32<<<WSZ/256, 256>>>(Wq, Whi + 0*WSZ, Wlo + 0*WSZ);
    split_f32<<<WSZ/256, 256>>>(Wk, Whi + 1*WSZ, Wlo + 1*WSZ);
    split_f32<<<WSZ/256, 256>>>(Wv, Whi + 2*WSZ, Wlo + 2*WSZ);
    split_f32<<<WSZ/256, 256>>>(Ww, Whi + 3*WSZ, Wlo + 3*WSZ);
    split_f32<<<WSZ/256, 256>>>(Wo, Whi + 4*WSZ, Wlo + 4*WSZ);

    // projections on tensor cores
    hgemm_abt<<<hgrid, 256, HGEMM_SMEM>>>(xhi, xlo, Whi + 0*WSZ, Wlo + 0*WSZ, q, DIN, 0, 0);
    hgemm_abt<<<hgrid, 256, HGEMM_SMEM>>>(xhi, xlo, Whi + 1*WSZ, Wlo + 1*WSZ, k, DIN, 0, 0);
    hgemm_abt<<<hgrid, 256, HGEMM_SMEM>>>(xhi, xlo, Whi + 2*WSZ, Wlo + 2*WSZ, v, DIN, 0, 0);
    hgemm_abt<<<hgrid, 256, HGEMM_SMEM>>>(xhi, xlo, Whi + 3*WSZ, Wlo + 3*WSZ, w, DIN, 0, 1);

    convert_q<<<(H*BNR*HD)/256, 256>>>();
    convert_k<<<(H*MEMS*HD)/256, 256>>>(kmem0);

    sims_topk<<<dim3(BNR/64, H), 256, SIMS_SMEM>>>();
    flash_attn<<<dim3(NN/64, H, BB), 256, FLASH_SMEM>>>(q, k, v, ao, NN);
    rescore_kernel<<<(H*BNR)/8, 256>>>(kmem0);
    gather_kernel<<<(BB*NN*IPQ*DIN)/256, 256>>>(kmem0, vmem0);
    flash_attn<<<dim3(NN/64, H, BB), 256, FLASH_SMEM>>>(q, km, vm, aom, NN*IPQ);

    // output projections on tensor cores (reuse a-plane buffers sequentially)
    split_f32<<<(BNR*DOUT)/256, 256>>>(ao, ahi, alo);
    hgemm_abt<<<hgrid, 256, HGEMM_SMEM>>>(ahi, alo, Whi + 4*WSZ, Wlo + 4*WSZ, c1, DOUT, bo, 0);
    split_f32<<<(BNR*DOUT)/256, 256>>>(aom, ahi, alo);
    hgemm_abt<<<hgrid, 256, HGEMM_SMEM>>>(ahi, alo, Whi + 4*WSZ, Wlo + 4*WSZ, c2, DOUT, bo, 0);

    combine_kernel<<<(BNR*DOUT)/256, 256>>>(out);
}